// round 2
// baseline (speedup 1.0000x reference)
#include <cuda_runtime.h>
#include <math.h>

#define Bv 16
#define Tv 600
#define Hv 512
#define Mv (Bv*Tv)          // 9600 rows
#define G4 (4*Hv)           // 2048 gate rows

// ---------------- scratch (device globals; no allocation) ----------------
__device__ float g_xt [Mv*Hv];        // x transposed [B*T, 512]
__device__ float g_xpf[Mv*G4];        // input-proj fwd  [B*T, 2048]
__device__ float g_xpb[Mv*G4];        // input-proj bwd
__device__ float g_h0 [Mv*2*Hv];      // layer0 output concat [B*T, 1024]
__device__ float g_h1 [Mv*2*Hv];      // layer1 output concat
__device__ float g_fc [Mv*Hv];        // fc output pre-LN
__device__ int   g_flags[128];        // per-block arrival flags (no shared-atomic hot spot)

// ---------------- transpose x[B,H,T] -> g_xt[(b*T+t)*H + h] ----------------
__global__ void k_transpose(const float* __restrict__ x)
{
    __shared__ float tile[32][33];
    int bb = blockIdx.z;
    int t0 = blockIdx.x * 32, h0 = blockIdx.y * 32;
    int tx = threadIdx.x, ty = threadIdx.y;
    #pragma unroll
    for (int i = 0; i < 4; i++) {
        int hh = h0 + ty + i*8;
        int tt = t0 + tx;
        if (tt < Tv) tile[ty + i*8][tx] = x[(bb*Hv + hh)*Tv + tt];
    }
    __syncthreads();
    #pragma unroll
    for (int i = 0; i < 4; i++) {
        int tt = t0 + ty + i*8;
        int hh = h0 + tx;
        if (tt < Tv) g_xt[(bb*Tv + tt)*Hv + hh] = tile[tx][ty + i*8];
    }
}

// ---------------- C[M,N] = A[M,K] @ W[N,K]^T + bias[N] ----------------
// BM=128, BN=64, BK=16, 256 threads, 8x4 per thread.
__global__ __launch_bounds__(256, 2) void k_gemm(const float* __restrict__ A,
                                                 const float* __restrict__ W,
                                                 const float* __restrict__ bias,
                                                 float* __restrict__ C,
                                                 int K, int N)
{
    __shared__ __align__(16) float As[16][132];
    __shared__ __align__(16) float Ws[16][68];
    const int tid = threadIdx.x;
    const int tx = tid & 15;        // n-group (0..15) -> 4 cols
    const int ty = tid >> 4;        // m-group (0..15) -> 8 rows
    const int m0 = blockIdx.y * 128, n0 = blockIdx.x * 64;

    float acc[8][4] = {};
    for (int kb = 0; kb < K; kb += 16) {
        #pragma unroll
        for (int i = 0; i < 2; i++) {
            int s = tid + i*256;
            int r = s >> 2, k4 = (s & 3) * 4;
            float4 v = *(const float4*)&A[(size_t)(m0 + r)*K + kb + k4];
            As[k4+0][r] = v.x; As[k4+1][r] = v.y;
            As[k4+2][r] = v.z; As[k4+3][r] = v.w;
        }
        {
            int r = tid >> 2, k4 = (tid & 3) * 4;
            float4 v = *(const float4*)&W[(size_t)(n0 + r)*K + kb + k4];
            Ws[k4+0][r] = v.x; Ws[k4+1][r] = v.y;
            Ws[k4+2][r] = v.z; Ws[k4+3][r] = v.w;
        }
        __syncthreads();
        #pragma unroll
        for (int k = 0; k < 16; k++) {
            float4 a0 = *(const float4*)&As[k][ty*8];
            float4 a1 = *(const float4*)&As[k][ty*8+4];
            float4 w  = *(const float4*)&Ws[k][tx*4];
            float am[8] = {a0.x,a0.y,a0.z,a0.w,a1.x,a1.y,a1.z,a1.w};
            #pragma unroll
            for (int i = 0; i < 8; i++) {
                acc[i][0] = fmaf(am[i], w.x, acc[i][0]);
                acc[i][1] = fmaf(am[i], w.y, acc[i][1]);
                acc[i][2] = fmaf(am[i], w.z, acc[i][2]);
                acc[i][3] = fmaf(am[i], w.w, acc[i][3]);
            }
        }
        __syncthreads();
    }
    float4 bv = *(const float4*)&bias[n0 + tx*4];
    #pragma unroll
    for (int i = 0; i < 8; i++) {
        float4 o;
        o.x = acc[i][0] + bv.x; o.y = acc[i][1] + bv.y;
        o.z = acc[i][2] + bv.z; o.w = acc[i][3] + bv.w;
        *(float4*)&C[(size_t)(m0 + ty*8 + i)*N + n0 + tx*4] = o;
    }
}

// ---------------- barrier reset ----------------
__global__ void k_reset() { g_flags[threadIdx.x] = 0; }

// ---------------- persistent bidirectional LSTM layer ----------------
// 128 blocks: [0,64) forward, [64,128) backward. Block owns 8 hidden units
// (32 gate rows). w_hh slice in SMEM; c state in SMEM; flag-array grid barrier.
__global__ __launch_bounds__(256, 1) void k_lstm(const float* __restrict__ xpf,
                                                 const float* __restrict__ xpb,
                                                 const float* __restrict__ whhf,
                                                 const float* __restrict__ whhb,
                                                 float* __restrict__ hout)
{
    extern __shared__ float sm[];
    float* w_s  = sm;                 // [32][516]
    float* h_s  = w_s + 32*516;       // [16][516]
    float* xp_s = h_s + 16*516;       // [32][16]
    float* g_s  = xp_s + 512;         // [32][16]
    float* c_s  = g_s + 512;          // [128]  (j*16+b)

    const int tid   = threadIdx.x;
    const int bid   = blockIdx.x;
    const int dir   = bid >> 6;
    const int slice = bid & 63;
    const int u0    = slice * 8;
    const float* xp  = dir ? xpb  : xpf;
    const float* whh = dir ? whhb : whhf;

    // stage w_hh slice: 32 rows x 512 (rows: gate*512 + u0 + j)
    for (int idx = tid; idx < 32*128; idx += 256) {
        int lr = idx >> 7, k4 = (idx & 127) * 4;
        int gr = (lr >> 3) * 512 + u0 + (lr & 7);
        float4 v = *(const float4*)&whh[(size_t)gr * 512 + k4];
        *(float4*)&w_s[lr*516 + k4] = v;
    }
    if (tid < 128) c_s[tid] = 0.f;

    const int lane = tid & 31;
    const int wi   = tid >> 5;
    const int b    = lane & 15;
    const int lr0  = wi*4 + (lane >> 4)*2;
    const int lr1  = lr0 + 1;
    const float* wr0 = w_s + lr0*516;
    const float* wr1 = w_s + lr1*516;
    const float* hr  = h_s + b*516;

    for (int s = 0; s < Tv; s++) {
        int t = dir ? (Tv-1 - s) : s;
        if (s == 0) {
            for (int idx = tid; idx < 16*516; idx += 256) h_s[idx] = 0.f;
        } else {
            int tp = dir ? t + 1 : t - 1;
            for (int idx = tid; idx < 2048; idx += 256) {
                int bb = idx >> 7, k4 = (idx & 127) * 4;
                *(float4*)&h_s[bb*516 + k4] =
                    *(const float4*)&hout[(size_t)(bb*Tv + tp)*1024 + dir*512 + k4];
            }
        }
        // stage xp slice for (all b, our 32 gate rows) at time t
        for (int idx = tid; idx < 512; idx += 256) {
            int j = idx & 7, seg = idx >> 3;
            int bb = seg & 15, gate = seg >> 4;
            xp_s[(gate*8 + j)*16 + bb] =
                xp[(size_t)(bb*Tv + t)*2048 + gate*512 + u0 + j];
        }
        __syncthreads();

        // 2 dot products of length 512 per thread (batch b, rows lr0/lr1)
        float a0 = 0.f, a1 = 0.f;
        #pragma unroll 4
        for (int k = 0; k < 512; k += 4) {
            float4 hv = *(const float4*)&hr[k];
            float4 w0 = *(const float4*)&wr0[k];
            float4 w1 = *(const float4*)&wr1[k];
            a0 = fmaf(hv.x,w0.x, fmaf(hv.y,w0.y, fmaf(hv.z,w0.z, fmaf(hv.w,w0.w, a0))));
            a1 = fmaf(hv.x,w1.x, fmaf(hv.y,w1.y, fmaf(hv.z,w1.z, fmaf(hv.w,w1.w, a1))));
        }
        g_s[lr0*16 + b] = a0 + xp_s[lr0*16 + b];
        g_s[lr1*16 + b] = a1 + xp_s[lr1*16 + b];
        __syncthreads();

        if (tid < 128) {
            int bb = tid & 15, j = tid >> 4;
            float gi = g_s[( 0 + j)*16 + bb];
            float gf = g_s[( 8 + j)*16 + bb];
            float gg = g_s[(16 + j)*16 + bb];
            float go = g_s[(24 + j)*16 + bb];
            float iv = __fdividef(1.f, 1.f + __expf(-gi));
            float fv = __fdividef(1.f, 1.f + __expf(-gf));
            float gv = tanhf(gg);
            float ov = __fdividef(1.f, 1.f + __expf(-go));
            float c  = fv * c_s[tid] + iv * gv;
            c_s[tid] = c;
            hout[(size_t)(bb*Tv + t)*1024 + dir*512 + u0 + j] = ov * tanhf(c);
        }
        // distributed-flag grid barrier (128 co-resident blocks, no atomics)
        __threadfence();
        __syncthreads();
        if (tid == 0) ((volatile int*)g_flags)[bid] = s + 1;
        if (tid < 128) {
            while (((volatile int*)g_flags)[tid] < s + 1) { }
            __threadfence();
        }
        __syncthreads();
    }
}

// ---------------- LayerNorm + ReLU (warp per row of 512) ----------------
__global__ __launch_bounds__(256) void k_lnrelu(const float* __restrict__ in,
                                                const float* __restrict__ lnw,
                                                const float* __restrict__ lnb,
                                                float* __restrict__ out)
{
    int row  = blockIdx.x * 8 + (threadIdx.x >> 5);
    int lane = threadIdx.x & 31;
    const float* p = in + (size_t)row * 512;
    float4 v[4];
    float s = 0.f, s2 = 0.f;
    #pragma unroll
    for (int i = 0; i < 4; i++) {
        v[i] = *(const float4*)&p[i*128 + lane*4];
        s  += v[i].x + v[i].y + v[i].z + v[i].w;
        s2 += v[i].x*v[i].x + v[i].y*v[i].y + v[i].z*v[i].z + v[i].w*v[i].w;
    }
    #pragma unroll
    for (int o = 16; o; o >>= 1) {
        s  += __shfl_xor_sync(0xffffffffu, s,  o);
        s2 += __shfl_xor_sync(0xffffffffu, s2, o);
    }
    float mu   = s * (1.f/512.f);
    float var  = s2 * (1.f/512.f) - mu*mu;
    float rstd = rsqrtf(var + 1e-5f);
    float* q = out + (size_t)row * 512;
    #pragma unroll
    for (int i = 0; i < 4; i++) {
        int k = i*128 + lane*4;
        float4 wv = *(const float4*)&lnw[k];
        float4 bv = *(const float4*)&lnb[k];
        float4 o4;
        o4.x = fmaxf((v[i].x - mu)*rstd*wv.x + bv.x, 0.f);
        o4.y = fmaxf((v[i].y - mu)*rstd*wv.y + bv.y, 0.f);
        o4.z = fmaxf((v[i].z - mu)*rstd*wv.z + bv.z, 0.f);
        o4.w = fmaxf((v[i].w - mu)*rstd*wv.w + bv.w, 0.f);
        *(float4*)&q[k] = o4;
    }
}

// ---------------- host ----------------
extern "C" void kernel_launch(void* const* d_in, const int* in_sizes, int n_in,
                              void* d_out, int out_size)
{
    const float* x       = (const float*)d_in[0];
    const float* wih_l0f = (const float*)d_in[1];
    const float* whh_l0f = (const float*)d_in[2];
    const float* b_l0f   = (const float*)d_in[3];
    const float* wih_l0b = (const float*)d_in[4];
    const float* whh_l0b = (const float*)d_in[5];
    const float* b_l0b   = (const float*)d_in[6];
    const float* wih_l1f = (const float*)d_in[7];
    const float* whh_l1f = (const float*)d_in[8];
    const float* b_l1f   = (const float*)d_in[9];
    const float* wih_l1b = (const float*)d_in[10];
    const float* whh_l1b = (const float*)d_in[11];
    const float* b_l1b   = (const float*)d_in[12];
    const float* fc_w    = (const float*)d_in[13];
    const float* fc_b    = (const float*)d_in[14];
    const float* ln_w    = (const float*)d_in[15];
    const float* ln_b    = (const float*)d_in[16];
    float* out = (float*)d_out;

    void *p_xt, *p_xpf, *p_xpb, *p_h0, *p_h1, *p_fc;
    cudaGetSymbolAddress(&p_xt,  g_xt);
    cudaGetSymbolAddress(&p_xpf, g_xpf);
    cudaGetSymbolAddress(&p_xpb, g_xpb);
    cudaGetSymbolAddress(&p_h0,  g_h0);
    cudaGetSymbolAddress(&p_h1,  g_h1);
    cudaGetSymbolAddress(&p_fc,  g_fc);

    const size_t LSTM_SMEM = (32*516 + 16*516 + 512 + 512 + 128) * sizeof(float); // 103680 B
    cudaFuncSetAttribute(k_lstm, cudaFuncAttributeMaxDynamicSharedMemorySize, (int)LSTM_SMEM);

    // transpose input
    k_transpose<<<dim3(19, 16, 16), dim3(32, 8)>>>(x);

    // layer 0 input projections
    k_gemm<<<dim3(32, 75), 256>>>((const float*)p_xt, wih_l0f, b_l0f, (float*)p_xpf, 512, 2048);
    k_gemm<<<dim3(32, 75), 256>>>((const float*)p_xt, wih_l0b, b_l0b, (float*)p_xpb, 512, 2048);
    // layer 0 recurrence
    k_reset<<<1, 128>>>();
    k_lstm<<<128, 256, LSTM_SMEM>>>((const float*)p_xpf, (const float*)p_xpb,
                                    whh_l0f, whh_l0b, (float*)p_h0);
    // layer 1 input projections (K = 1024)
    k_gemm<<<dim3(32, 75), 256>>>((const float*)p_h0, wih_l1f, b_l1f, (float*)p_xpf, 1024, 2048);
    k_gemm<<<dim3(32, 75), 256>>>((const float*)p_h0, wih_l1b, b_l1b, (float*)p_xpb, 1024, 2048);
    // layer 1 recurrence
    k_reset<<<1, 128>>>();
    k_lstm<<<128, 256, LSTM_SMEM>>>((const float*)p_xpf, (const float*)p_xpb,
                                    whh_l1f, whh_l1b, (float*)p_h1);
    // fc + layernorm + relu
    k_gemm<<<dim3(8, 75), 256>>>((const float*)p_h1, fc_w, fc_b, (float*)p_fc, 1024, 512);
    k_lnrelu<<<1200, 256>>>((const float*)p_fc, ln_w, ln_b, out);
}

// round 3
// speedup vs baseline: 2.1005x; 2.1005x over previous
#include <cuda_runtime.h>
#include <math.h>

#define Bv 16
#define Tv 600
#define Hv 512
#define Mv (Bv*Tv)          // 9600 rows
#define G4 (4*Hv)           // 2048 gate rows

// ---------------- scratch (device globals; no allocation) ----------------
__device__ float g_xt [Mv*Hv];        // x transposed [B*T, 512]
__device__ float g_xpf[Mv*G4];        // input-proj fwd  [B*T, 2048]
__device__ float g_xpb[Mv*G4];        // input-proj bwd
__device__ float g_h0 [Mv*2*Hv];      // layer0 output concat [B*T, 1024]
__device__ float g_h1 [Mv*2*Hv];      // layer1 output concat
__device__ float g_fc [Mv*Hv];        // fc output pre-LN
__device__ unsigned g_ctr[64];        // per-direction step counters: [0]=fwd, [32]=bwd

// ---------------- f32x2 packed helpers ----------------
__device__ __forceinline__ unsigned long long ffma2(unsigned long long a,
                                                    unsigned long long b,
                                                    unsigned long long c)
{
    unsigned long long d;
    asm("fma.rn.f32x2 %0, %1, %2, %3;" : "=l"(d) : "l"(a), "l"(b), "l"(c));
    return d;
}
__device__ __forceinline__ unsigned long long pk(float a, float b)
{
    unsigned long long v;
    asm("mov.b64 %0, {%1, %2};" : "=l"(v) : "f"(a), "f"(b));
    return v;
}
__device__ __forceinline__ float2 unpk(unsigned long long v)
{
    float2 r;
    asm("mov.b64 {%0, %1}, %2;" : "=f"(r.x), "=f"(r.y) : "l"(v));
    return r;
}
__device__ __forceinline__ unsigned ld_acq(const unsigned* p)
{
    unsigned v;
    asm volatile("ld.acquire.gpu.global.u32 %0, [%1];" : "=r"(v) : "l"(p));
    return v;
}

// ---------------- transpose x[B,H,T] -> g_xt[(b*T+t)*H + h] ----------------
__global__ void k_transpose(const float* __restrict__ x)
{
    __shared__ float tile[32][33];
    int bb = blockIdx.z;
    int t0 = blockIdx.x * 32, h0 = blockIdx.y * 32;
    int tx = threadIdx.x, ty = threadIdx.y;
    #pragma unroll
    for (int i = 0; i < 4; i++) {
        int hh = h0 + ty + i*8;
        int tt = t0 + tx;
        if (tt < Tv) tile[ty + i*8][tx] = x[(bb*Hv + hh)*Tv + tt];
    }
    __syncthreads();
    #pragma unroll
    for (int i = 0; i < 4; i++) {
        int tt = t0 + ty + i*8;
        int hh = h0 + tx;
        if (tt < Tv) g_xt[(bb*Tv + tt)*Hv + hh] = tile[tx][ty + i*8];
    }
}

// ---------------- C[M,N] = A[M,K] @ W[N,K]^T + bias[N] ----------------
// BM=BN=64, BK=16, 256 threads, 4x4 per thread, FFMA2 inner loop.
__global__ __launch_bounds__(256) void k_gemm(const float* __restrict__ A,
                                              const float* __restrict__ W,
                                              const float* __restrict__ bias,
                                              float* __restrict__ C,
                                              int K, int N)
{
    __shared__ __align__(16) float As[16][68];
    __shared__ __align__(16) float Ws[16][68];
    const int tid = threadIdx.x;
    const int tx = tid & 15, ty = tid >> 4;
    const int m0 = blockIdx.y * 64, n0 = blockIdx.x * 64;
    const int lrow = tid >> 2;            // 0..63
    const int lk   = (tid & 3) * 4;       // 0,4,8,12
    const float* Ap = A + (size_t)(m0 + lrow) * K + lk;
    const float* Wp = W + (size_t)(n0 + lrow) * K + lk;

    // acc[j][p]: packed pair of M-rows (ty*4+2p, ty*4+2p+1) at column tx*4+j
    unsigned long long acc[4][2] = {};
    for (int kb = 0; kb < K; kb += 16) {
        float4 va = *(const float4*)(Ap + kb);
        float4 vw = *(const float4*)(Wp + kb);
        As[lk+0][lrow] = va.x; As[lk+1][lrow] = va.y;
        As[lk+2][lrow] = va.z; As[lk+3][lrow] = va.w;
        Ws[lk+0][lrow] = vw.x; Ws[lk+1][lrow] = vw.y;
        Ws[lk+2][lrow] = vw.z; Ws[lk+3][lrow] = vw.w;
        __syncthreads();
        #pragma unroll
        for (int k = 0; k < 16; k++) {
            ulonglong2 ap = *(const ulonglong2*)&As[k][ty*4];
            float4 w = *(const float4*)&Ws[k][tx*4];
            unsigned long long w0 = pk(w.x, w.x);
            unsigned long long w1 = pk(w.y, w.y);
            unsigned long long w2 = pk(w.z, w.z);
            unsigned long long w3 = pk(w.w, w.w);
            acc[0][0] = ffma2(ap.x, w0, acc[0][0]);
            acc[0][1] = ffma2(ap.y, w0, acc[0][1]);
            acc[1][0] = ffma2(ap.x, w1, acc[1][0]);
            acc[1][1] = ffma2(ap.y, w1, acc[1][1]);
            acc[2][0] = ffma2(ap.x, w2, acc[2][0]);
            acc[2][1] = ffma2(ap.y, w2, acc[2][1]);
            acc[3][0] = ffma2(ap.x, w3, acc[3][0]);
            acc[3][1] = ffma2(ap.y, w3, acc[3][1]);
        }
        __syncthreads();
    }
    float4 bv = *(const float4*)&bias[n0 + tx*4];
    float2 up[4][2];
    #pragma unroll
    for (int j = 0; j < 4; j++) {
        up[j][0] = unpk(acc[j][0]);
        up[j][1] = unpk(acc[j][1]);
    }
    #pragma unroll
    for (int i = 0; i < 4; i++) {
        int p = i >> 1;
        float4 o;
        o.x = ((i & 1) ? up[0][p].y : up[0][p].x) + bv.x;
        o.y = ((i & 1) ? up[1][p].y : up[1][p].x) + bv.y;
        o.z = ((i & 1) ? up[2][p].y : up[2][p].x) + bv.z;
        o.w = ((i & 1) ? up[3][p].y : up[3][p].x) + bv.w;
        *(float4*)&C[(size_t)(m0 + ty*4 + i) * N + n0 + tx*4] = o;
    }
}

// ---------------- barrier reset ----------------
__global__ void k_reset() { g_ctr[threadIdx.x] = 0u; }

// ---------------- persistent bidirectional LSTM layer ----------------
// 128 blocks: [0,64) forward, [64,128) backward. Block owns 8 hidden units.
// Warp wi handles unit j=wi: lanes 0-15 (b=lane) gates i,f; lanes 16-31 gates g,o.
// Gate combine via shuffles; cell state c in registers; per-direction counter barrier.
__global__ __launch_bounds__(256, 1) void k_lstm(const float* __restrict__ xpf,
                                                 const float* __restrict__ xpb,
                                                 const float* __restrict__ whhf,
                                                 const float* __restrict__ whhb,
                                                 float* __restrict__ hout)
{
    extern __shared__ float sm[];
    float* w_s = sm;                  // [32][516]
    float* h_s = w_s + 32*516;        // [16][516]

    const int tid   = threadIdx.x;
    const int bid   = blockIdx.x;
    const int dir   = bid >> 6;
    const int u0    = (bid & 63) * 8;
    const float* xp  = dir ? xpb  : xpf;
    const float* whh = dir ? whhb : whhf;
    unsigned* ctr = &g_ctr[dir * 32];

    // stage w_hh slice: 32 rows x 512 (row lr: gate=lr>>3, j=lr&7)
    for (int idx = tid; idx < 32*128; idx += 256) {
        int lr = idx >> 7, k4 = (idx & 127) * 4;
        int gr = (lr >> 3) * 512 + u0 + (lr & 7);
        float4 v = *(const float4*)&whh[(size_t)gr * 512 + k4];
        *(float4*)&w_s[lr*516 + k4] = v;
    }

    const int lane = tid & 31;
    const int wi   = tid >> 5;        // j = wi
    const int b    = lane & 15;
    const int half = lane >> 4;       // 0: gates (i,f); 1: gates (g,o)
    const int gA   = half * 2;
    const float* wrA = w_s + (gA*8 + wi)*516;
    const float* wrB = w_s + ((gA+1)*8 + wi)*516;
    const float* hr  = h_s + b*516;

    const size_t xpA_base = (size_t)b*Tv*2048 + (size_t)gA*512 + u0 + wi;
    const size_t hw_base  = (size_t)b*Tv*1024 + dir*512 + u0 + wi;  // + t*1024

    float c = 0.f;
    // prefetch xp for step 0
    int t0i = dir ? (Tv-1) : 0;
    float xpA = xp[xpA_base + (size_t)t0i*2048];
    float xpB = xp[xpA_base + 512 + (size_t)t0i*2048];

    for (int s = 0; s < Tv; s++) {
        int t = dir ? (Tv-1 - s) : s;
        if (s > 0) {
            if (tid == 0) {
                unsigned target = 64u * (unsigned)s;
                while ((int)(ld_acq(ctr) - target) < 0) { }
            }
            __syncthreads();
            int tp = dir ? t + 1 : t - 1;
            for (int idx = tid; idx < 2048; idx += 256) {
                int bb = idx >> 7, k4 = (idx & 127) * 4;
                *(float4*)&h_s[bb*516 + k4] =
                    *(const float4*)&hout[(size_t)(bb*Tv + tp)*1024 + dir*512 + k4];
            }
        } else {
            for (int idx = tid; idx < 16*516; idx += 256) h_s[idx] = 0.f;
        }
        __syncthreads();

        // two packed dot products of length 512 (gates gA, gA+1 for batch b)
        unsigned long long accA0 = 0ull, accA1 = 0ull, accB0 = 0ull, accB1 = 0ull;
        #pragma unroll 4
        for (int k = 0; k < 512; k += 4) {
            ulonglong2 hv = *(const ulonglong2*)&hr[k];
            ulonglong2 wa = *(const ulonglong2*)&wrA[k];
            ulonglong2 wb = *(const ulonglong2*)&wrB[k];
            accA0 = ffma2(hv.x, wa.x, accA0);
            accA1 = ffma2(hv.y, wa.y, accA1);
            accB0 = ffma2(hv.x, wb.x, accB0);
            accB1 = ffma2(hv.y, wb.y, accB1);
        }
        float2 uA0 = unpk(accA0), uA1 = unpk(accA1);
        float2 uB0 = unpk(accB0), uB1 = unpk(accB1);
        float aA = (uA0.x + uA0.y) + (uA1.x + uA1.y) + xpA;
        float aB = (uB0.x + uB0.y) + (uB1.x + uB1.y) + xpB;

        // lanes<16 fetch (g,o) preactivations from lanes+16
        float gPre = __shfl_down_sync(0xffffffffu, aA, 16);
        float oPre = __shfl_down_sync(0xffffffffu, aB, 16);

        // prefetch next step's xp (independent of the grid barrier)
        if (s + 1 < Tv) {
            int tn = dir ? (Tv-2 - s) : (s + 1);
            xpA = xp[xpA_base + (size_t)tn*2048];
            xpB = xp[xpA_base + 512 + (size_t)tn*2048];
        }

        if (half == 0) {
            float iv = __fdividef(1.f, 1.f + __expf(-aA));
            float fv = __fdividef(1.f, 1.f + __expf(-aB));
            float gv = tanhf(gPre);
            float ov = __fdividef(1.f, 1.f + __expf(-oPre));
            c = fv * c + iv * gv;
            hout[hw_base + (size_t)t*1024] = ov * tanhf(c);
        }

        // arrive: fence writes, then one REDG per block on this direction's counter
        __threadfence();
        __syncthreads();
        if (tid == 0) atomicAdd(ctr, 1u);
    }
}

// ---------------- LayerNorm + ReLU (warp per row of 512) ----------------
__global__ __launch_bounds__(256) void k_lnrelu(const float* __restrict__ in,
                                                const float* __restrict__ lnw,
                                                const float* __restrict__ lnb,
                                                float* __restrict__ out)
{
    int row  = blockIdx.x * 8 + (threadIdx.x >> 5);
    int lane = threadIdx.x & 31;
    const float* p = in + (size_t)row * 512;
    float4 v[4];
    float s = 0.f, s2 = 0.f;
    #pragma unroll
    for (int i = 0; i < 4; i++) {
        v[i] = *(const float4*)&p[i*128 + lane*4];
        s  += v[i].x + v[i].y + v[i].z + v[i].w;
        s2 += v[i].x*v[i].x + v[i].y*v[i].y + v[i].z*v[i].z + v[i].w*v[i].w;
    }
    #pragma unroll
    for (int o = 16; o; o >>= 1) {
        s  += __shfl_xor_sync(0xffffffffu, s,  o);
        s2 += __shfl_xor_sync(0xffffffffu, s2, o);
    }
    float mu   = s * (1.f/512.f);
    float var  = s2 * (1.f/512.f) - mu*mu;
    float rstd = rsqrtf(var + 1e-5f);
    float* q = out + (size_t)row * 512;
    #pragma unroll
    for (int i = 0; i < 4; i++) {
        int k = i*128 + lane*4;
        float4 wv = *(const float4*)&lnw[k];
        float4 bv = *(const float4*)&lnb[k];
        float4 o4;
        o4.x = fmaxf((v[i].x - mu)*rstd*wv.x + bv.x, 0.f);
        o4.y = fmaxf((v[i].y - mu)*rstd*wv.y + bv.y, 0.f);
        o4.z = fmaxf((v[i].z - mu)*rstd*wv.z + bv.z, 0.f);
        o4.w = fmaxf((v[i].w - mu)*rstd*wv.w + bv.w, 0.f);
        *(float4*)&q[k] = o4;
    }
}

// ---------------- host ----------------
extern "C" void kernel_launch(void* const* d_in, const int* in_sizes, int n_in,
                              void* d_out, int out_size)
{
    const float* x       = (const float*)d_in[0];
    const float* wih_l0f = (const float*)d_in[1];
    const float* whh_l0f = (const float*)d_in[2];
    const float* b_l0f   = (const float*)d_in[3];
    const float* wih_l0b = (const float*)d_in[4];
    const float* whh_l0b = (const float*)d_in[5];
    const float* b_l0b   = (const float*)d_in[6];
    const float* wih_l1f = (const float*)d_in[7];
    const float* whh_l1f = (const float*)d_in[8];
    const float* b_l1f   = (const float*)d_in[9];
    const float* wih_l1b = (const float*)d_in[10];
    const float* whh_l1b = (const float*)d_in[11];
    const float* b_l1b   = (const float*)d_in[12];
    const float* fc_w    = (const float*)d_in[13];
    const float* fc_b    = (const float*)d_in[14];
    const float* ln_w    = (const float*)d_in[15];
    const float* ln_b    = (const float*)d_in[16];
    float* out = (float*)d_out;

    void *p_xt, *p_xpf, *p_xpb, *p_h0, *p_h1, *p_fc;
    cudaGetSymbolAddress(&p_xt,  g_xt);
    cudaGetSymbolAddress(&p_xpf, g_xpf);
    cudaGetSymbolAddress(&p_xpb, g_xpb);
    cudaGetSymbolAddress(&p_h0,  g_h0);
    cudaGetSymbolAddress(&p_h1,  g_h1);
    cudaGetSymbolAddress(&p_fc,  g_fc);

    const size_t LSTM_SMEM = (32*516 + 16*516) * sizeof(float); // 99072 B
    cudaFuncSetAttribute(k_lstm, cudaFuncAttributeMaxDynamicSharedMemorySize, (int)LSTM_SMEM);

    // transpose input
    k_transpose<<<dim3(19, 16, 16), dim3(32, 8)>>>(x);

    // layer 0 input projections
    k_gemm<<<dim3(32, 150), 256>>>((const float*)p_xt, wih_l0f, b_l0f, (float*)p_xpf, 512, 2048);
    k_gemm<<<dim3(32, 150), 256>>>((const float*)p_xt, wih_l0b, b_l0b, (float*)p_xpb, 512, 2048);
    // layer 0 recurrence
    k_reset<<<1, 64>>>();
    k_lstm<<<128, 256, LSTM_SMEM>>>((const float*)p_xpf, (const float*)p_xpb,
                                    whh_l0f, whh_l0b, (float*)p_h0);
    // layer 1 input projections (K = 1024)
    k_gemm<<<dim3(32, 150), 256>>>((const float*)p_h0, wih_l1f, b_l1f, (float*)p_xpf, 1024, 2048);
    k_gemm<<<dim3(32, 150), 256>>>((const float*)p_h0, wih_l1b, b_l1b, (float*)p_xpb, 1024, 2048);
    // layer 1 recurrence
    k_reset<<<1, 64>>>();
    k_lstm<<<128, 256, LSTM_SMEM>>>((const float*)p_xpf, (const float*)p_xpb,
                                    whh_l1f, whh_l1b, (float*)p_h1);
    // fc + layernorm + relu
    k_gemm<<<dim3(8, 150), 256>>>((const float*)p_h1, fc_w, fc_b, (float*)p_fc, 1024, 512);
    k_lnrelu<<<1200, 256>>>((const float*)p_fc, ln_w, ln_b, out);
}

// round 4
// speedup vs baseline: 2.2518x; 1.0720x over previous
#include <cuda_runtime.h>
#include <math.h>

#define Bv 16
#define Tv 600
#define Hv 512
#define Mv (Bv*Tv)          // 9600 rows
#define G4 (4*Hv)           // 2048 gate rows

// ---------------- scratch (device globals; no allocation) ----------------
__device__ float g_xt [Mv*Hv];        // x transposed [B*T, 512]
__device__ float g_xpf[Mv*G4];        // input-proj fwd  [B*T, 2048]
__device__ float g_xpb[Mv*G4];        // input-proj bwd
__device__ float g_h0 [Mv*2*Hv];      // layer0 output concat [B*T, 1024]
__device__ float g_h1 [Mv*2*Hv];      // layer1 output concat
__device__ float g_fc [Mv*Hv];        // fc output pre-LN
__device__ unsigned g_ctrA[64];       // layer0 step counters: [0]=fwd, [32]=bwd
__device__ unsigned g_ctrB[64];       // layer1 step counters

// ---------------- f32x2 packed helpers ----------------
__device__ __forceinline__ unsigned long long ffma2(unsigned long long a,
                                                    unsigned long long b,
                                                    unsigned long long c)
{
    unsigned long long d;
    asm("fma.rn.f32x2 %0, %1, %2, %3;" : "=l"(d) : "l"(a), "l"(b), "l"(c));
    return d;
}
__device__ __forceinline__ unsigned long long pk(float a, float b)
{
    unsigned long long v;
    asm("mov.b64 %0, {%1, %2};" : "=l"(v) : "f"(a), "f"(b));
    return v;
}
__device__ __forceinline__ float2 unpk(unsigned long long v)
{
    float2 r;
    asm("mov.b64 {%0, %1}, %2;" : "=f"(r.x), "=f"(r.y) : "l"(v));
    return r;
}
__device__ __forceinline__ unsigned ld_acq(const unsigned* p)
{
    unsigned v;
    asm volatile("ld.acquire.gpu.global.u32 %0, [%1];" : "=r"(v) : "l"(p));
    return v;
}
__device__ __forceinline__ void red_release(unsigned* p)
{
    asm volatile("red.release.gpu.global.add.u32 [%0], 1;" :: "l"(p) : "memory");
}
__device__ __forceinline__ float fast_sig(float x)
{
    return __fdividef(1.f, 1.f + __expf(-x));
}
__device__ __forceinline__ float fast_tanh(float x)
{
    return 1.f - 2.f * __fdividef(1.f, __expf(2.f * x) + 1.f);
}

// ---------------- transpose x[B,H,T] -> g_xt[(b*T+t)*H + h] ----------------
// Also resets both LSTM step-counter arrays (block 0 only).
__global__ void k_transpose(const float* __restrict__ x)
{
    if (blockIdx.x == 0 && blockIdx.y == 0 && blockIdx.z == 0) {
        int id = threadIdx.y * 32 + threadIdx.x;
        if (id < 64)       g_ctrA[id] = 0u;
        else if (id < 128) g_ctrB[id - 64] = 0u;
    }
    __shared__ float tile[32][33];
    int bb = blockIdx.z;
    int t0 = blockIdx.x * 32, h0 = blockIdx.y * 32;
    int tx = threadIdx.x, ty = threadIdx.y;
    #pragma unroll
    for (int i = 0; i < 4; i++) {
        int hh = h0 + ty + i*8;
        int tt = t0 + tx;
        if (tt < Tv) tile[ty + i*8][tx] = x[(bb*Hv + hh)*Tv + tt];
    }
    __syncthreads();
    #pragma unroll
    for (int i = 0; i < 4; i++) {
        int tt = t0 + ty + i*8;
        int hh = h0 + tx;
        if (tt < Tv) g_xt[(bb*Tv + tt)*Hv + hh] = tile[tx][ty + i*8];
    }
}

// ---------------- C[M,N] = A[M,K] @ W[N,K]^T + bias[N] ----------------
// BM=BN=64, BK=16, 256 threads, 4x4 per thread, FFMA2 inner loop.
__global__ __launch_bounds__(256) void k_gemm(const float* __restrict__ A,
                                              const float* __restrict__ W,
                                              const float* __restrict__ bias,
                                              float* __restrict__ C,
                                              int K, int N)
{
    __shared__ __align__(16) float As[16][68];
    __shared__ __align__(16) float Ws[16][68];
    const int tid = threadIdx.x;
    const int tx = tid & 15, ty = tid >> 4;
    const int m0 = blockIdx.y * 64, n0 = blockIdx.x * 64;
    const int lrow = tid >> 2;            // 0..63
    const int lk   = (tid & 3) * 4;       // 0,4,8,12
    const float* Ap = A + (size_t)(m0 + lrow) * K + lk;
    const float* Wp = W + (size_t)(n0 + lrow) * K + lk;

    unsigned long long acc[4][2] = {};
    for (int kb = 0; kb < K; kb += 16) {
        float4 va = *(const float4*)(Ap + kb);
        float4 vw = *(const float4*)(Wp + kb);
        As[lk+0][lrow] = va.x; As[lk+1][lrow] = va.y;
        As[lk+2][lrow] = va.z; As[lk+3][lrow] = va.w;
        Ws[lk+0][lrow] = vw.x; Ws[lk+1][lrow] = vw.y;
        Ws[lk+2][lrow] = vw.z; Ws[lk+3][lrow] = vw.w;
        __syncthreads();
        #pragma unroll
        for (int k = 0; k < 16; k++) {
            ulonglong2 ap = *(const ulonglong2*)&As[k][ty*4];
            float4 w = *(const float4*)&Ws[k][tx*4];
            unsigned long long w0 = pk(w.x, w.x);
            unsigned long long w1 = pk(w.y, w.y);
            unsigned long long w2 = pk(w.z, w.z);
            unsigned long long w3 = pk(w.w, w.w);
            acc[0][0] = ffma2(ap.x, w0, acc[0][0]);
            acc[0][1] = ffma2(ap.y, w0, acc[0][1]);
            acc[1][0] = ffma2(ap.x, w1, acc[1][0]);
            acc[1][1] = ffma2(ap.y, w1, acc[1][1]);
            acc[2][0] = ffma2(ap.x, w2, acc[2][0]);
            acc[2][1] = ffma2(ap.y, w2, acc[2][1]);
            acc[3][0] = ffma2(ap.x, w3, acc[3][0]);
            acc[3][1] = ffma2(ap.y, w3, acc[3][1]);
        }
        __syncthreads();
    }
    float4 bv = *(const float4*)&bias[n0 + tx*4];
    float2 up[4][2];
    #pragma unroll
    for (int j = 0; j < 4; j++) {
        up[j][0] = unpk(acc[j][0]);
        up[j][1] = unpk(acc[j][1]);
    }
    #pragma unroll
    for (int i = 0; i < 4; i++) {
        int p = i >> 1;
        float4 o;
        o.x = ((i & 1) ? up[0][p].y : up[0][p].x) + bv.x;
        o.y = ((i & 1) ? up[1][p].y : up[1][p].x) + bv.y;
        o.z = ((i & 1) ? up[2][p].y : up[2][p].x) + bv.z;
        o.w = ((i & 1) ? up[3][p].y : up[3][p].x) + bv.w;
        *(float4*)&C[(size_t)(m0 + ty*4 + i) * N + n0 + tx*4] = o;
    }
}

// ---------------- persistent bidirectional LSTM layer ----------------
// 128 blocks: [0,64) forward, [64,128) backward. Block owns 8 hidden units.
// Warp wi = unit. Lane = kq*8 + bpair: thread computes 4 gates x 2 batches
// (bpair, bpair+8) over k-quarter [kq*128, kq*128+128). shfl_xor allreduce
// over kq; lanes 0-15 (b = lane) do the cell update. Counter barrier / step.
__global__ __launch_bounds__(256, 1) void k_lstm(const float* __restrict__ xpf,
                                                 const float* __restrict__ xpb,
                                                 const float* __restrict__ whhf,
                                                 const float* __restrict__ whhb,
                                                 float* __restrict__ hout,
                                                 unsigned* __restrict__ ctrbase)
{
    extern __shared__ float sm[];
    float* w_s = sm;                  // [32][516]
    float* h_s = w_s + 32*516;        // [16][516]

    const int tid   = threadIdx.x;
    const int bid   = blockIdx.x;
    const int dir   = bid >> 6;
    const int u0    = (bid & 63) * 8;
    const float* xp  = dir ? xpb  : xpf;
    const float* whh = dir ? whhb : whhf;
    unsigned* ctr = ctrbase + dir * 32;

    // stage w_hh slice: 32 rows x 512 (row lr: gate=lr>>3, j=lr&7)
    for (int idx = tid; idx < 32*128; idx += 256) {
        int lr = idx >> 7, k4 = (idx & 127) * 4;
        int gr = (lr >> 3) * 512 + u0 + (lr & 7);
        float4 v = *(const float4*)&whh[(size_t)gr * 512 + k4];
        *(float4*)&w_s[lr*516 + k4] = v;
    }

    const int lane  = tid & 31;
    const int wi    = tid >> 5;       // unit j = wi
    const int bpair = lane & 7;
    const int kq    = lane >> 3;      // k-quarter
    const int kb0   = kq * 128;
    const float* wr0 = w_s + (0*8 + wi)*516 + kb0;
    const float* wr1 = w_s + (1*8 + wi)*516 + kb0;
    const float* wr2 = w_s + (2*8 + wi)*516 + kb0;
    const float* wr3 = w_s + (3*8 + wi)*516 + kb0;
    const float* hr0 = h_s + bpair*516 + kb0;
    const float* hr1 = hr0 + 8*516;

    // activation-lane constants (lanes 0-15: b = lane)
    const int  bmy     = lane;        // only valid lane<16
    const size_t xbase = (size_t)bmy*Tv*2048 + u0 + wi;       // + t*2048 + g*512
    const size_t hwb   = (size_t)bmy*Tv*1024 + dir*512 + u0 + wi;  // + t*1024

    float c = 0.f;
    float xq0=0.f, xq1=0.f, xq2=0.f, xq3=0.f;
    {
        int t0i = dir ? (Tv-1) : 0;
        if (lane < 16) {
            const float* p = xp + xbase + (size_t)t0i*2048;
            xq0 = p[0]; xq1 = p[512]; xq2 = p[1024]; xq3 = p[1536];
        }
    }

    for (int s = 0; s < Tv; s++) {
        int t = dir ? (Tv-1 - s) : s;
        if (s > 0) {
            if (tid == 0) {
                unsigned target = 64u * (unsigned)s;
                while ((int)(ld_acq(ctr) - target) < 0) { }
            }
            __syncthreads();
            int tp = dir ? t + 1 : t - 1;
            for (int idx = tid; idx < 2048; idx += 256) {
                int bb = idx >> 7, k4 = (idx & 127) * 4;
                *(float4*)&h_s[bb*516 + k4] =
                    *(const float4*)&hout[(size_t)(bb*Tv + tp)*1024 + dir*512 + k4];
            }
        } else {
            for (int idx = tid; idx < 16*516; idx += 256) h_s[idx] = 0.f;
        }
        __syncthreads();

        // 4 gates x 2 batches over this thread's k-quarter (packed f32x2)
        unsigned long long a00=0,a01=0,a10=0,a11=0,a20=0,a21=0,a30=0,a31=0;
        #pragma unroll 2
        for (int k = 0; k < 128; k += 4) {
            ulonglong2 h0 = *(const ulonglong2*)&hr0[k];
            ulonglong2 h1 = *(const ulonglong2*)&hr1[k];
            ulonglong2 w0 = *(const ulonglong2*)&wr0[k];
            ulonglong2 w1 = *(const ulonglong2*)&wr1[k];
            ulonglong2 w2 = *(const ulonglong2*)&wr2[k];
            ulonglong2 w3 = *(const ulonglong2*)&wr3[k];
            a00 = ffma2(h0.x, w0.x, a00); a00 = ffma2(h0.y, w0.y, a00);
            a01 = ffma2(h1.x, w0.x, a01); a01 = ffma2(h1.y, w0.y, a01);
            a10 = ffma2(h0.x, w1.x, a10); a10 = ffma2(h0.y, w1.y, a10);
            a11 = ffma2(h1.x, w1.x, a11); a11 = ffma2(h1.y, w1.y, a11);
            a20 = ffma2(h0.x, w2.x, a20); a20 = ffma2(h0.y, w2.y, a20);
            a21 = ffma2(h1.x, w2.x, a21); a21 = ffma2(h1.y, w2.y, a21);
            a30 = ffma2(h0.x, w3.x, a30); a30 = ffma2(h0.y, w3.y, a30);
            a31 = ffma2(h1.x, w3.x, a31); a31 = ffma2(h1.y, w3.y, a31);
        }
        float av[4][2];
        { float2 u;
          u = unpk(a00); av[0][0] = u.x + u.y;
          u = unpk(a01); av[0][1] = u.x + u.y;
          u = unpk(a10); av[1][0] = u.x + u.y;
          u = unpk(a11); av[1][1] = u.x + u.y;
          u = unpk(a20); av[2][0] = u.x + u.y;
          u = unpk(a21); av[2][1] = u.x + u.y;
          u = unpk(a30); av[3][0] = u.x + u.y;
          u = unpk(a31); av[3][1] = u.x + u.y; }
        // allreduce over the 4 kq lanes
        #pragma unroll
        for (int off = 8; off <= 16; off <<= 1) {
            #pragma unroll
            for (int g = 0; g < 4; g++) {
                av[g][0] += __shfl_xor_sync(0xffffffffu, av[g][0], off);
                av[g][1] += __shfl_xor_sync(0xffffffffu, av[g][1], off);
            }
        }

        // prefetch next step's xp (independent of the grid barrier)
        float nx0=0.f, nx1=0.f, nx2=0.f, nx3=0.f;
        if (s + 1 < Tv && lane < 16) {
            int tn = dir ? (Tv-2 - s) : (s + 1);
            const float* p = xp + xbase + (size_t)tn*2048;
            nx0 = p[0]; nx1 = p[512]; nx2 = p[1024]; nx3 = p[1536];
        }

        if (lane < 16) {
            int bi = lane >> 3;
            float gi = (bi ? av[0][1] : av[0][0]) + xq0;
            float gf = (bi ? av[1][1] : av[1][0]) + xq1;
            float gg = (bi ? av[2][1] : av[2][0]) + xq2;
            float go = (bi ? av[3][1] : av[3][0]) + xq3;
            float iv = fast_sig(gi);
            float fv = fast_sig(gf);
            float gv = fast_tanh(gg);
            float ov = fast_sig(go);
            c = fv * c + iv * gv;
            hout[hwb + (size_t)t*1024] = ov * fast_tanh(c);
        }
        xq0 = nx0; xq1 = nx1; xq2 = nx2; xq3 = nx3;

        // arrive: CTA barrier orders all STGs, then one release-red on counter
        __syncthreads();
        if (tid == 0) red_release(ctr);
    }
}

// ---------------- LayerNorm + ReLU (warp per row of 512) ----------------
__global__ __launch_bounds__(256) void k_lnrelu(const float* __restrict__ in,
                                                const float* __restrict__ lnw,
                                                const float* __restrict__ lnb,
                                                float* __restrict__ out)
{
    int row  = blockIdx.x * 8 + (threadIdx.x >> 5);
    int lane = threadIdx.x & 31;
    const float* p = in + (size_t)row * 512;
    float4 v[4];
    float s = 0.f, s2 = 0.f;
    #pragma unroll
    for (int i = 0; i < 4; i++) {
        v[i] = *(const float4*)&p[i*128 + lane*4];
        s  += v[i].x + v[i].y + v[i].z + v[i].w;
        s2 += v[i].x*v[i].x + v[i].y*v[i].y + v[i].z*v[i].z + v[i].w*v[i].w;
    }
    #pragma unroll
    for (int o = 16; o; o >>= 1) {
        s  += __shfl_xor_sync(0xffffffffu, s,  o);
        s2 += __shfl_xor_sync(0xffffffffu, s2, o);
    }
    float mu   = s * (1.f/512.f);
    float var  = s2 * (1.f/512.f) - mu*mu;
    float rstd = rsqrtf(var + 1e-5f);
    float* q = out + (size_t)row * 512;
    #pragma unroll
    for (int i = 0; i < 4; i++) {
        int k = i*128 + lane*4;
        float4 wv = *(const float4*)&lnw[k];
        float4 bv = *(const float4*)&lnb[k];
        float4 o4;
        o4.x = fmaxf((v[i].x - mu)*rstd*wv.x + bv.x, 0.f);
        o4.y = fmaxf((v[i].y - mu)*rstd*wv.y + bv.y, 0.f);
        o4.z = fmaxf((v[i].z - mu)*rstd*wv.z + bv.z, 0.f);
        o4.w = fmaxf((v[i].w - mu)*rstd*wv.w + bv.w, 0.f);
        *(float4*)&q[k] = o4;
    }
}

// ---------------- host ----------------
extern "C" void kernel_launch(void* const* d_in, const int* in_sizes, int n_in,
                              void* d_out, int out_size)
{
    const float* x       = (const float*)d_in[0];
    const float* wih_l0f = (const float*)d_in[1];
    const float* whh_l0f = (const float*)d_in[2];
    const float* b_l0f   = (const float*)d_in[3];
    const float* wih_l0b = (const float*)d_in[4];
    const float* whh_l0b = (const float*)d_in[5];
    const float* b_l0b   = (const float*)d_in[6];
    const float* wih_l1f = (const float*)d_in[7];
    const float* whh_l1f = (const float*)d_in[8];
    const float* b_l1f   = (const float*)d_in[9];
    const float* wih_l1b = (const float*)d_in[10];
    const float* whh_l1b = (const float*)d_in[11];
    const float* b_l1b   = (const float*)d_in[12];
    const float* fc_w    = (const float*)d_in[13];
    const float* fc_b    = (const float*)d_in[14];
    const float* ln_w    = (const float*)d_in[15];
    const float* ln_b    = (const float*)d_in[16];
    float* out = (float*)d_out;

    void *p_xt, *p_xpf, *p_xpb, *p_h0, *p_h1, *p_fc, *p_cA, *p_cB;
    cudaGetSymbolAddress(&p_xt,  g_xt);
    cudaGetSymbolAddress(&p_xpf, g_xpf);
    cudaGetSymbolAddress(&p_xpb, g_xpb);
    cudaGetSymbolAddress(&p_h0,  g_h0);
    cudaGetSymbolAddress(&p_h1,  g_h1);
    cudaGetSymbolAddress(&p_fc,  g_fc);
    cudaGetSymbolAddress(&p_cA,  g_ctrA);
    cudaGetSymbolAddress(&p_cB,  g_ctrB);

    const size_t LSTM_SMEM = (32*516 + 16*516) * sizeof(float); // 99072 B
    cudaFuncSetAttribute(k_lstm, cudaFuncAttributeMaxDynamicSharedMemorySize, (int)LSTM_SMEM);

    // 1: transpose input (+ reset both layers' barrier counters)
    k_transpose<<<dim3(19, 16, 16), dim3(32, 8)>>>(x);

    // 2,3: layer 0 input projections
    k_gemm<<<dim3(32, 150), 256>>>((const float*)p_xt, wih_l0f, b_l0f, (float*)p_xpf, 512, 2048);
    k_gemm<<<dim3(32, 150), 256>>>((const float*)p_xt, wih_l0b, b_l0b, (float*)p_xpb, 512, 2048);
    // 4: layer 0 recurrence  (<- ncu -s 5 captures this launch)
    k_lstm<<<128, 256, LSTM_SMEM>>>((const float*)p_xpf, (const float*)p_xpb,
                                    whh_l0f, whh_l0b, (float*)p_h0, (unsigned*)p_cA);
    // 5,6: layer 1 input projections (K = 1024)
    k_gemm<<<dim3(32, 150), 256>>>((const float*)p_h0, wih_l1f, b_l1f, (float*)p_xpf, 1024, 2048);
    k_gemm<<<dim3(32, 150), 256>>>((const float*)p_h0, wih_l1b, b_l1b, (float*)p_xpb, 1024, 2048);
    // 7: layer 1 recurrence
    k_lstm<<<128, 256, LSTM_SMEM>>>((const float*)p_xpf, (const float*)p_xpb,
                                    whh_l1f, whh_l1b, (float*)p_h1, (unsigned*)p_cB);
    // 8,9: fc + layernorm + relu
    k_gemm<<<dim3(8, 150), 256>>>((const float*)p_h1, fc_w, fc_b, (float*)p_fc, 1024, 512);
    k_lnrelu<<<1200, 256>>>((const float*)p_fc, ln_w, ln_b, out);
}

// round 5
// speedup vs baseline: 2.3980x; 1.0649x over previous
#include <cuda_runtime.h>
#include <math.h>

#define Bv 16
#define Tv 600
#define Hv 512
#define Mv (Bv*Tv)          // 9600 rows
#define G4 (4*Hv)           // 2048 gate rows

// ---------------- scratch (device globals; no allocation) ----------------
__device__ float g_xt [Mv*Hv];        // x transposed [B*T, 512]
__device__ float g_xpf[Mv*G4];        // input-proj fwd  [B*T, 2048]
__device__ float g_xpb[Mv*G4];        // input-proj bwd
__device__ float g_h0 [Mv*2*Hv];      // layer0 output concat [B*T, 1024]
__device__ float g_h1 [Mv*2*Hv];      // layer1 output concat
__device__ float g_fc [Mv*Hv];        // fc output pre-LN
__device__ unsigned g_ctrA[64];       // layer0 step counters: [0]=fwd, [32]=bwd
__device__ unsigned g_ctrB[64];       // layer1 step counters

// ---------------- f32x2 packed helpers (used in k_lstm only) ----------------
__device__ __forceinline__ unsigned long long ffma2(unsigned long long a,
                                                    unsigned long long b,
                                                    unsigned long long c)
{
    unsigned long long d;
    asm("fma.rn.f32x2 %0, %1, %2, %3;" : "=l"(d) : "l"(a), "l"(b), "l"(c));
    return d;
}
__device__ __forceinline__ float2 unpk(unsigned long long v)
{
    float2 r;
    asm("mov.b64 {%0, %1}, %2;" : "=f"(r.x), "=f"(r.y) : "l"(v));
    return r;
}
__device__ __forceinline__ unsigned ld_acq(const unsigned* p)
{
    unsigned v;
    asm volatile("ld.acquire.gpu.global.u32 %0, [%1];" : "=r"(v) : "l"(p));
    return v;
}
__device__ __forceinline__ void red_release(unsigned* p)
{
    asm volatile("red.release.gpu.global.add.u32 [%0], 1;" :: "l"(p) : "memory");
}
__device__ __forceinline__ float fast_sig(float x)
{
    return __fdividef(1.f, 1.f + __expf(-x));
}
__device__ __forceinline__ float fast_tanh(float x)
{
    return 1.f - 2.f * __fdividef(1.f, __expf(2.f * x) + 1.f);
}

// ---------------- transpose x[B,H,T] -> g_xt[(b*T+t)*H + h] ----------------
// Also resets both LSTM step-counter arrays (block 0 only).
__global__ void k_transpose(const float* __restrict__ x)
{
    if (blockIdx.x == 0 && blockIdx.y == 0 && blockIdx.z == 0) {
        int id = threadIdx.y * 32 + threadIdx.x;
        if (id < 64)       g_ctrA[id] = 0u;
        else if (id < 128) g_ctrB[id - 64] = 0u;
    }
    __shared__ float tile[32][33];
    int bb = blockIdx.z;
    int t0 = blockIdx.x * 32, h0 = blockIdx.y * 32;
    int tx = threadIdx.x, ty = threadIdx.y;
    #pragma unroll
    for (int i = 0; i < 4; i++) {
        int hh = h0 + ty + i*8;
        int tt = t0 + tx;
        if (tt < Tv) tile[ty + i*8][tx] = x[(bb*Hv + hh)*Tv + tt];
    }
    __syncthreads();
    #pragma unroll
    for (int i = 0; i < 4; i++) {
        int tt = t0 + ty + i*8;
        int hh = h0 + tx;
        if (tt < Tv) g_xt[(bb*Tv + tt)*Hv + hh] = tile[tx][ty + i*8];
    }
}

// ---------------- C[M,N] = A[M,K] @ W[N,K]^T + bias[N] ----------------
// BM=128, BN=64, BK=16, 256 threads, 8x4 per thread, plain FFMA.
__global__ __launch_bounds__(256, 2) void k_gemm(const float* __restrict__ A,
                                                 const float* __restrict__ W,
                                                 const float* __restrict__ bias,
                                                 float* __restrict__ C,
                                                 int K, int N)
{
    __shared__ __align__(16) float As[16][132];
    __shared__ __align__(16) float Ws[16][68];
    const int tid = threadIdx.x;
    const int tx = tid & 15;        // n-group (0..15) -> 4 cols
    const int ty = tid >> 4;        // m-group (0..15) -> 8 rows
    const int m0 = blockIdx.y * 128, n0 = blockIdx.x * 64;

    float acc[8][4] = {};
    for (int kb = 0; kb < K; kb += 16) {
        #pragma unroll
        for (int i = 0; i < 2; i++) {
            int s = tid + i*256;
            int r = s >> 2, k4 = (s & 3) * 4;
            float4 v = *(const float4*)&A[(size_t)(m0 + r)*K + kb + k4];
            As[k4+0][r] = v.x; As[k4+1][r] = v.y;
            As[k4+2][r] = v.z; As[k4+3][r] = v.w;
        }
        {
            int r = tid >> 2, k4 = (tid & 3) * 4;
            float4 v = *(const float4*)&W[(size_t)(n0 + r)*K + kb + k4];
            Ws[k4+0][r] = v.x; Ws[k4+1][r] = v.y;
            Ws[k4+2][r] = v.z; Ws[k4+3][r] = v.w;
        }
        __syncthreads();
        #pragma unroll
        for (int k = 0; k < 16; k++) {
            float4 a0 = *(const float4*)&As[k][ty*8];
            float4 a1 = *(const float4*)&As[k][ty*8+4];
            float4 w  = *(const float4*)&Ws[k][tx*4];
            float am[8] = {a0.x,a0.y,a0.z,a0.w,a1.x,a1.y,a1.z,a1.w};
            #pragma unroll
            for (int i = 0; i < 8; i++) {
                acc[i][0] = fmaf(am[i], w.x, acc[i][0]);
                acc[i][1] = fmaf(am[i], w.y, acc[i][1]);
                acc[i][2] = fmaf(am[i], w.z, acc[i][2]);
                acc[i][3] = fmaf(am[i], w.w, acc[i][3]);
            }
        }
        __syncthreads();
    }
    float4 bv = *(const float4*)&bias[n0 + tx*4];
    #pragma unroll
    for (int i = 0; i < 8; i++) {
        float4 o;
        o.x = acc[i][0] + bv.x; o.y = acc[i][1] + bv.y;
        o.z = acc[i][2] + bv.z; o.w = acc[i][3] + bv.w;
        *(float4*)&C[(size_t)(m0 + ty*8 + i)*N + n0 + tx*4] = o;
    }
}

// ---------------- persistent bidirectional LSTM layer ----------------
// 128 blocks: [0,64) forward, [64,128) backward. Block owns 8 hidden units.
// Warp wi = unit. Lane = kq*8 + bpair: thread computes 4 gates x 2 batches
// (bpair, bpair+8) over k-quarter [kq*128, kq*128+128). shfl_xor allreduce
// over kq; lanes 0-15 (b = lane) do the cell update. Counter barrier / step.
__global__ __launch_bounds__(256, 1) void k_lstm(const float* __restrict__ xpf,
                                                 const float* __restrict__ xpb,
                                                 const float* __restrict__ whhf,
                                                 const float* __restrict__ whhb,
                                                 float* __restrict__ hout,
                                                 unsigned* __restrict__ ctrbase)
{
    extern __shared__ float sm[];
    float* w_s = sm;                  // [32][516]
    float* h_s = w_s + 32*516;        // [16][516]

    const int tid   = threadIdx.x;
    const int bid   = blockIdx.x;
    const int dir   = bid >> 6;
    const int u0    = (bid & 63) * 8;
    const float* xp  = dir ? xpb  : xpf;
    const float* whh = dir ? whhb : whhf;
    unsigned* ctr = ctrbase + dir * 32;

    // stage w_hh slice: 32 rows x 512 (row lr: gate=lr>>3, j=lr&7)
    for (int idx = tid; idx < 32*128; idx += 256) {
        int lr = idx >> 7, k4 = (idx & 127) * 4;
        int gr = (lr >> 3) * 512 + u0 + (lr & 7);
        float4 v = *(const float4*)&whh[(size_t)gr * 512 + k4];
        *(float4*)&w_s[lr*516 + k4] = v;
    }

    const int lane  = tid & 31;
    const int wi    = tid >> 5;       // unit j = wi
    const int bpair = lane & 7;
    const int kq    = lane >> 3;      // k-quarter
    const int kb0   = kq * 128;
    const float* wr0 = w_s + (0*8 + wi)*516 + kb0;
    const float* wr1 = w_s + (1*8 + wi)*516 + kb0;
    const float* wr2 = w_s + (2*8 + wi)*516 + kb0;
    const float* wr3 = w_s + (3*8 + wi)*516 + kb0;
    const float* hr0 = h_s + bpair*516 + kb0;
    const float* hr1 = hr0 + 8*516;

    // activation-lane constants (lanes 0-15: b = lane)
    const int  bmy     = lane;        // only valid lane<16
    const size_t xbase = (size_t)bmy*Tv*2048 + u0 + wi;       // + t*2048 + g*512
    const size_t hwb   = (size_t)bmy*Tv*1024 + dir*512 + u0 + wi;  // + t*1024

    float c = 0.f;
    float xq0=0.f, xq1=0.f, xq2=0.f, xq3=0.f;
    {
        int t0i = dir ? (Tv-1) : 0;
        if (lane < 16) {
            const float* p = xp + xbase + (size_t)t0i*2048;
            xq0 = p[0]; xq1 = p[512]; xq2 = p[1024]; xq3 = p[1536];
        }
    }

    for (int s = 0; s < Tv; s++) {
        int t = dir ? (Tv-1 - s) : s;
        if (s > 0) {
            if (tid == 0) {
                unsigned target = 64u * (unsigned)s;
                while ((int)(ld_acq(ctr) - target) < 0) { }
            }
            __syncthreads();
            int tp = dir ? t + 1 : t - 1;
            for (int idx = tid; idx < 2048; idx += 256) {
                int bb = idx >> 7, k4 = (idx & 127) * 4;
                *(float4*)&h_s[bb*516 + k4] =
                    *(const float4*)&hout[(size_t)(bb*Tv + tp)*1024 + dir*512 + k4];
            }
        } else {
            for (int idx = tid; idx < 16*516; idx += 256) h_s[idx] = 0.f;
        }
        __syncthreads();

        // 4 gates x 2 batches over this thread's k-quarter (packed f32x2)
        unsigned long long a00=0,a01=0,a10=0,a11=0,a20=0,a21=0,a30=0,a31=0;
        #pragma unroll 2
        for (int k = 0; k < 128; k += 4) {
            ulonglong2 h0 = *(const ulonglong2*)&hr0[k];
            ulonglong2 h1 = *(const ulonglong2*)&hr1[k];
            ulonglong2 w0 = *(const ulonglong2*)&wr0[k];
            ulonglong2 w1 = *(const ulonglong2*)&wr1[k];
            ulonglong2 w2 = *(const ulonglong2*)&wr2[k];
            ulonglong2 w3 = *(const ulonglong2*)&wr3[k];
            a00 = ffma2(h0.x, w0.x, a00); a00 = ffma2(h0.y, w0.y, a00);
            a01 = ffma2(h1.x, w0.x, a01); a01 = ffma2(h1.y, w0.y, a01);
            a10 = ffma2(h0.x, w1.x, a10); a10 = ffma2(h0.y, w1.y, a10);
            a11 = ffma2(h1.x, w1.x, a11); a11 = ffma2(h1.y, w1.y, a11);
            a20 = ffma2(h0.x, w2.x, a20); a20 = ffma2(h0.y, w2.y, a20);
            a21 = ffma2(h1.x, w2.x, a21); a21 = ffma2(h1.y, w2.y, a21);
            a30 = ffma2(h0.x, w3.x, a30); a30 = ffma2(h0.y, w3.y, a30);
            a31 = ffma2(h1.x, w3.x, a31); a31 = ffma2(h1.y, w3.y, a31);
        }
        float av[4][2];
        { float2 u;
          u = unpk(a00); av[0][0] = u.x + u.y;
          u = unpk(a01); av[0][1] = u.x + u.y;
          u = unpk(a10); av[1][0] = u.x + u.y;
          u = unpk(a11); av[1][1] = u.x + u.y;
          u = unpk(a20); av[2][0] = u.x + u.y;
          u = unpk(a21); av[2][1] = u.x + u.y;
          u = unpk(a30); av[3][0] = u.x + u.y;
          u = unpk(a31); av[3][1] = u.x + u.y; }
        // allreduce over the 4 kq lanes
        #pragma unroll
        for (int off = 8; off <= 16; off <<= 1) {
            #pragma unroll
            for (int g = 0; g < 4; g++) {
                av[g][0] += __shfl_xor_sync(0xffffffffu, av[g][0], off);
                av[g][1] += __shfl_xor_sync(0xffffffffu, av[g][1], off);
            }
        }

        // prefetch next step's xp (independent of the grid barrier)
        float nx0=0.f, nx1=0.f, nx2=0.f, nx3=0.f;
        if (s + 1 < Tv && lane < 16) {
            int tn = dir ? (Tv-2 - s) : (s + 1);
            const float* p = xp + xbase + (size_t)tn*2048;
            nx0 = p[0]; nx1 = p[512]; nx2 = p[1024]; nx3 = p[1536];
        }

        if (lane < 16) {
            int bi = lane >> 3;
            float gi = (bi ? av[0][1] : av[0][0]) + xq0;
            float gf = (bi ? av[1][1] : av[1][0]) + xq1;
            float gg = (bi ? av[2][1] : av[2][0]) + xq2;
            float go = (bi ? av[3][1] : av[3][0]) + xq3;
            float iv = fast_sig(gi);
            float fv = fast_sig(gf);
            float gv = fast_tanh(gg);
            float ov = fast_sig(go);
            c = fv * c + iv * gv;
            hout[hwb + (size_t)t*1024] = ov * fast_tanh(c);
        }
        xq0 = nx0; xq1 = nx1; xq2 = nx2; xq3 = nx3;

        // arrive: CTA barrier orders all STGs, then one release-red on counter
        __syncthreads();
        if (tid == 0) red_release(ctr);
    }
}

// ---------------- LayerNorm + ReLU (warp per row of 512) ----------------
__global__ __launch_bounds__(256) void k_lnrelu(const float* __restrict__ in,
                                                const float* __restrict__ lnw,
                                                const float* __restrict__ lnb,
                                                float* __restrict__ out)
{
    int row  = blockIdx.x * 8 + (threadIdx.x >> 5);
    int lane = threadIdx.x & 31;
    const float* p = in + (size_t)row * 512;
    float4 v[4];
    float s = 0.f, s2 = 0.f;
    #pragma unroll
    for (int i = 0; i < 4; i++) {
        v[i] = *(const float4*)&p[i*128 + lane*4];
        s  += v[i].x + v[i].y + v[i].z + v[i].w;
        s2 += v[i].x*v[i].x + v[i].y*v[i].y + v[i].z*v[i].z + v[i].w*v[i].w;
    }
    #pragma unroll
    for (int o = 16; o; o >>= 1) {
        s  += __shfl_xor_sync(0xffffffffu, s,  o);
        s2 += __shfl_xor_sync(0xffffffffu, s2, o);
    }
    float mu   = s * (1.f/512.f);
    float var  = s2 * (1.f/512.f) - mu*mu;
    float rstd = rsqrtf(var + 1e-5f);
    float* q = out + (size_t)row * 512;
    #pragma unroll
    for (int i = 0; i < 4; i++) {
        int k = i*128 + lane*4;
        float4 wv = *(const float4*)&lnw[k];
        float4 bv = *(const float4*)&lnb[k];
        float4 o4;
        o4.x = fmaxf((v[i].x - mu)*rstd*wv.x + bv.x, 0.f);
        o4.y = fmaxf((v[i].y - mu)*rstd*wv.y + bv.y, 0.f);
        o4.z = fmaxf((v[i].z - mu)*rstd*wv.z + bv.z, 0.f);
        o4.w = fmaxf((v[i].w - mu)*rstd*wv.w + bv.w, 0.f);
        *(float4*)&q[k] = o4;
    }
}

// ---------------- host ----------------
extern "C" void kernel_launch(void* const* d_in, const int* in_sizes, int n_in,
                              void* d_out, int out_size)
{
    const float* x       = (const float*)d_in[0];
    const float* wih_l0f = (const float*)d_in[1];
    const float* whh_l0f = (const float*)d_in[2];
    const float* b_l0f   = (const float*)d_in[3];
    const float* wih_l0b = (const float*)d_in[4];
    const float* whh_l0b = (const float*)d_in[5];
    const float* b_l0b   = (const float*)d_in[6];
    const float* wih_l1f = (const float*)d_in[7];
    const float* whh_l1f = (const float*)d_in[8];
    const float* b_l1f   = (const float*)d_in[9];
    const float* wih_l1b = (const float*)d_in[10];
    const float* whh_l1b = (const float*)d_in[11];
    const float* b_l1b   = (const float*)d_in[12];
    const float* fc_w    = (const float*)d_in[13];
    const float* fc_b    = (const float*)d_in[14];
    const float* ln_w    = (const float*)d_in[15];
    const float* ln_b    = (const float*)d_in[16];
    float* out = (float*)d_out;

    void *p_xt, *p_xpf, *p_xpb, *p_h0, *p_h1, *p_fc, *p_cA, *p_cB;
    cudaGetSymbolAddress(&p_xt,  g_xt);
    cudaGetSymbolAddress(&p_xpf, g_xpf);
    cudaGetSymbolAddress(&p_xpb, g_xpb);
    cudaGetSymbolAddress(&p_h0,  g_h0);
    cudaGetSymbolAddress(&p_h1,  g_h1);
    cudaGetSymbolAddress(&p_fc,  g_fc);
    cudaGetSymbolAddress(&p_cA,  g_ctrA);
    cudaGetSymbolAddress(&p_cB,  g_ctrB);

    const size_t LSTM_SMEM = (32*516 + 16*516) * sizeof(float); // 99072 B
    cudaFuncSetAttribute(k_lstm, cudaFuncAttributeMaxDynamicSharedMemorySize, (int)LSTM_SMEM);

    // 1: transpose input (+ reset both layers' barrier counters)
    k_transpose<<<dim3(19, 16, 16), dim3(32, 8)>>>(x);

    // 2: layer 0 fwd projection (full)
    k_gemm<<<dim3(32, 75), 256>>>((const float*)p_xt, wih_l0f, b_l0f, (float*)p_xpf, 512, 2048);
    // 3,4: layer 0 bwd projection split in two N-halves (launch #4 = profiled GEMM)
    k_gemm<<<dim3(16, 75), 256>>>((const float*)p_xt, wih_l0b, b_l0b, (float*)p_xpb, 512, 2048);
    k_gemm<<<dim3(16, 75), 256>>>((const float*)p_xt, wih_l0b + (size_t)1024*512,
                                  b_l0b + 1024, (float*)p_xpb + 1024, 512, 2048);
    // 5: layer 0 recurrence
    k_lstm<<<128, 256, LSTM_SMEM>>>((const float*)p_xpf, (const float*)p_xpb,
                                    whh_l0f, whh_l0b, (float*)p_h0, (unsigned*)p_cA);
    // 6,7: layer 1 input projections (K = 1024)
    k_gemm<<<dim3(32, 75), 256>>>((const float*)p_h0, wih_l1f, b_l1f, (float*)p_xpf, 1024, 2048);
    k_gemm<<<dim3(32, 75), 256>>>((const float*)p_h0, wih_l1b, b_l1b, (float*)p_xpb, 1024, 2048);
    // 8: layer 1 recurrence
    k_lstm<<<128, 256, LSTM_SMEM>>>((const float*)p_xpf, (const float*)p_xpb,
                                    whh_l1f, whh_l1b, (float*)p_h1, (unsigned*)p_cB);
    // 9,10: fc + layernorm + relu
    k_gemm<<<dim3(8, 75), 256>>>((const float*)p_h1, fc_w, fc_b, (float*)p_fc, 1024, 512);
    k_lnrelu<<<1200, 256>>>((const float*)p_fc, ln_w, ln_b, out);
}

// round 6
// speedup vs baseline: 2.7316x; 1.1391x over previous
#include <cuda_runtime.h>
#include <math.h>

#define Bv 16
#define Tv 600
#define Hv 512
#define Mv (Bv*Tv)          // 9600 rows
#define G4 (4*Hv)           // 2048 gate rows

// ---------------- scratch (device globals; no allocation) ----------------
__device__ float g_xt [Mv*Hv];        // x transposed [B*T, 512]
__device__ float g_xpf[Mv*G4];        // input-proj fwd  [B*T, 2048]
__device__ float g_xpb[Mv*G4];        // input-proj bwd
__device__ float g_h0 [Mv*2*Hv];      // layer0 output concat [B*T, 1024]
__device__ float g_h1 [Mv*2*Hv];      // layer1 output concat
__device__ float g_fc [Mv*Hv];        // fc output pre-LN
__device__ unsigned g_ctrA[64];       // layer0 step counters: [0]=fwd, [32]=bwd
__device__ unsigned g_ctrB[64];       // layer1 step counters

// ---------------- f32x2 packed helpers (used in k_lstm only) ----------------
__device__ __forceinline__ unsigned long long ffma2(unsigned long long a,
                                                    unsigned long long b,
                                                    unsigned long long c)
{
    unsigned long long d;
    asm("fma.rn.f32x2 %0, %1, %2, %3;" : "=l"(d) : "l"(a), "l"(b), "l"(c));
    return d;
}
__device__ __forceinline__ float2 unpk(unsigned long long v)
{
    float2 r;
    asm("mov.b64 {%0, %1}, %2;" : "=f"(r.x), "=f"(r.y) : "l"(v));
    return r;
}
__device__ __forceinline__ unsigned ld_acq(const unsigned* p)
{
    unsigned v;
    asm volatile("ld.acquire.gpu.global.u32 %0, [%1];" : "=r"(v) : "l"(p));
    return v;
}
__device__ __forceinline__ void red_release(unsigned* p)
{
    asm volatile("red.release.gpu.global.add.u32 [%0], 1;" :: "l"(p) : "memory");
}
__device__ __forceinline__ float fast_sig(float x)
{
    return __fdividef(1.f, 1.f + __expf(-x));
}
__device__ __forceinline__ float fast_tanh(float x)
{
    return 1.f - 2.f * __fdividef(1.f, __expf(2.f * x) + 1.f);
}
// 4-way register select (compiles to SELs, no local memory)
#define SEL4(a0,a1,a2,a3,i) ((i) < 2 ? ((i)==0 ? (a0) : (a1)) : ((i)==2 ? (a2) : (a3)))

// ---------------- transpose x[B,H,T] -> g_xt[(b*T+t)*H + h] ----------------
// Also resets both LSTM step-counter arrays (block 0 only).
__global__ void k_transpose(const float* __restrict__ x)
{
    if (blockIdx.x == 0 && blockIdx.y == 0 && blockIdx.z == 0) {
        int id = threadIdx.y * 32 + threadIdx.x;
        if (id < 64)       g_ctrA[id] = 0u;
        else if (id < 128) g_ctrB[id - 64] = 0u;
    }
    __shared__ float tile[32][33];
    int bb = blockIdx.z;
    int t0 = blockIdx.x * 32, h0 = blockIdx.y * 32;
    int tx = threadIdx.x, ty = threadIdx.y;
    #pragma unroll
    for (int i = 0; i < 4; i++) {
        int hh = h0 + ty + i*8;
        int tt = t0 + tx;
        if (tt < Tv) tile[ty + i*8][tx] = x[(bb*Hv + hh)*Tv + tt];
    }
    __syncthreads();
    #pragma unroll
    for (int i = 0; i < 4; i++) {
        int tt = t0 + ty + i*8;
        int hh = h0 + tx;
        if (tt < Tv) g_xt[(bb*Tv + tt)*Hv + hh] = tile[tx][ty + i*8];
    }
}

// ---------------- C[M,N] = A[M,K] @ W[N,K]^T + bias[N] ----------------
// BM=128, BN=128, BK=16, 256 threads, 8x8 per thread (two 4x4 quads at
// column offsets {0,64} -> conflict-free stride-4 LDS).
__global__ __launch_bounds__(256, 2) void k_gemm(const float* __restrict__ A,
                                                 const float* __restrict__ W,
                                                 const float* __restrict__ bias,
                                                 float* __restrict__ C,
                                                 int K, int N)
{
    __shared__ __align__(16) float As[16][132];
    __shared__ __align__(16) float Ws[16][132];
    const int tid = threadIdx.x;
    const int tx = tid & 15;        // n-quad selector
    const int ty = tid >> 4;        // m-quad selector
    const int m0 = blockIdx.y * 128, n0 = blockIdx.x * 128;

    float acc[8][8] = {};
    for (int kb = 0; kb < K; kb += 16) {
        #pragma unroll
        for (int i = 0; i < 2; i++) {
            int s = tid + i*256;
            int r = s >> 2, k4 = (s & 3) * 4;
            float4 v = *(const float4*)&A[(size_t)(m0 + r)*K + kb + k4];
            As[k4+0][r] = v.x; As[k4+1][r] = v.y;
            As[k4+2][r] = v.z; As[k4+3][r] = v.w;
            float4 u = *(const float4*)&W[(size_t)(n0 + r)*K + kb + k4];
            Ws[k4+0][r] = u.x; Ws[k4+1][r] = u.y;
            Ws[k4+2][r] = u.z; Ws[k4+3][r] = u.w;
        }
        __syncthreads();
        #pragma unroll
        for (int k = 0; k < 16; k++) {
            float4 a0 = *(const float4*)&As[k][ty*4];
            float4 a1 = *(const float4*)&As[k][64 + ty*4];
            float4 w0 = *(const float4*)&Ws[k][tx*4];
            float4 w1 = *(const float4*)&Ws[k][64 + tx*4];
            float am[8] = {a0.x,a0.y,a0.z,a0.w,a1.x,a1.y,a1.z,a1.w};
            float wn[8] = {w0.x,w0.y,w0.z,w0.w,w1.x,w1.y,w1.z,w1.w};
            #pragma unroll
            for (int mi = 0; mi < 8; mi++) {
                #pragma unroll
                for (int ni = 0; ni < 8; ni++)
                    acc[mi][ni] = fmaf(am[mi], wn[ni], acc[mi][ni]);
            }
        }
        __syncthreads();
    }
    float4 bv0 = *(const float4*)&bias[n0 + tx*4];
    float4 bv1 = *(const float4*)&bias[n0 + 64 + tx*4];
    #pragma unroll
    for (int mi = 0; mi < 8; mi++) {
        int row = m0 + ((mi < 4) ? (ty*4 + mi) : (64 + ty*4 + mi - 4));
        float4 o0, o1;
        o0.x = acc[mi][0] + bv0.x; o0.y = acc[mi][1] + bv0.y;
        o0.z = acc[mi][2] + bv0.z; o0.w = acc[mi][3] + bv0.w;
        o1.x = acc[mi][4] + bv1.x; o1.y = acc[mi][5] + bv1.y;
        o1.z = acc[mi][6] + bv1.z; o1.w = acc[mi][7] + bv1.w;
        *(float4*)&C[(size_t)row*N + n0 + tx*4]      = o0;
        *(float4*)&C[(size_t)row*N + n0 + 64 + tx*4] = o1;
    }
}

// ---------------- persistent bidirectional LSTM layer ----------------
// 128 blocks: [0,64) forward, [64,128) backward. Block owns 8 hidden units.
// Warp wi = unit. Lane = bq*8 + ksl: thread computes 4 gates x 4 batches
// (bq*4..bq*4+3) over k-slice [ksl*64, ksl*64+64). smem k-slices padded to 68
// floats -> conflict-free stride-68 access. 3-round shfl_xor allreduce over
// ksl; lanes with (lane&4)==0 do the cell update. Counter barrier per step.
__global__ __launch_bounds__(256, 1) void k_lstm(const float* __restrict__ xpf,
                                                 const float* __restrict__ xpb,
                                                 const float* __restrict__ whhf,
                                                 const float* __restrict__ whhb,
                                                 float* __restrict__ hout,
                                                 unsigned* __restrict__ ctrbase)
{
    extern __shared__ float sm[];
    float* w_s = sm;                  // [32][544]  (8 slices x 68 per row)
    float* h_s = w_s + 32*544;        // [16][544]

    const int tid   = threadIdx.x;
    const int bid   = blockIdx.x;
    const int dir   = bid >> 6;
    const int u0    = (bid & 63) * 8;
    const float* xp  = dir ? xpb  : xpf;
    const float* whh = dir ? whhb : whhf;
    unsigned* ctr = ctrbase + dir * 32;

    // stage w_hh slice: 32 rows x 512 (row lr: gate=lr>>3, j=lr&7)
    for (int idx = tid; idx < 32*128; idx += 256) {
        int lr = idx >> 7, k = (idx & 127) * 4;
        int gr = (lr >> 3) * 512 + u0 + (lr & 7);
        float4 v = *(const float4*)&whh[(size_t)gr * 512 + k];
        *(float4*)&w_s[lr*544 + (k >> 6)*68 + (k & 63)] = v;
    }

    const int lane = tid & 31;
    const int wi   = tid >> 5;        // unit j = wi
    const int ksl  = lane & 7;        // k-slice (64 wide)
    const int bq   = lane >> 3;       // batch quad
    const int kof  = ksl * 68;
    const float* wg0 = w_s + (0*8 + wi)*544 + kof;
    const float* wg1 = w_s + (1*8 + wi)*544 + kof;
    const float* wg2 = w_s + (2*8 + wi)*544 + kof;
    const float* wg3 = w_s + (3*8 + wi)*544 + kof;
    const float* hr0 = h_s + (bq*4)*544 + kof;
    const float* hr1 = hr0 + 544;
    const float* hr2 = hr0 + 1088;
    const float* hr3 = hr0 + 1632;

    // activation lanes: (lane & 4) == 0; batch = bq*4 + (lane&3)
    const bool act = (lane & 4) == 0;
    const int  isel = lane & 3;
    const int  bmy  = bq*4 + isel;
    const size_t xbase = (size_t)bmy*Tv*2048 + u0 + wi;            // + t*2048 + g*512
    const size_t hwb   = (size_t)bmy*Tv*1024 + dir*512 + u0 + wi;  // + t*1024

    float c = 0.f;
    float xq0=0.f, xq1=0.f, xq2=0.f, xq3=0.f;
    {
        int t0i = dir ? (Tv-1) : 0;
        if (act) {
            const float* p = xp + xbase + (size_t)t0i*2048;
            xq0 = p[0]; xq1 = p[512]; xq2 = p[1024]; xq3 = p[1536];
        }
    }

    for (int s = 0; s < Tv; s++) {
        int t = dir ? (Tv-1 - s) : s;
        if (s > 0) {
            if (tid == 0) {
                unsigned target = 64u * (unsigned)s;
                while ((int)(ld_acq(ctr) - target) < 0) { }
            }
            __syncthreads();
            int tp = dir ? t + 1 : t - 1;
            for (int idx = tid; idx < 2048; idx += 256) {
                int bb = idx >> 7, k = (idx & 127) * 4;
                *(float4*)&h_s[bb*544 + (k >> 6)*68 + (k & 63)] =
                    *(const float4*)&hout[(size_t)(bb*Tv + tp)*1024 + dir*512 + k];
            }
        } else {
            for (int idx = tid; idx < 16*544; idx += 256) h_s[idx] = 0.f;
        }
        __syncthreads();

        // 4 gates x 4 batches over this thread's 64-k slice (packed f32x2)
        unsigned long long A00=0,A01=0,A02=0,A03=0, A10=0,A11=0,A12=0,A13=0,
                           A20=0,A21=0,A22=0,A23=0, A30=0,A31=0,A32=0,A33=0;
        #pragma unroll 2
        for (int k = 0; k < 64; k += 4) {
            ulonglong2 h0 = *(const ulonglong2*)&hr0[k];
            ulonglong2 h1 = *(const ulonglong2*)&hr1[k];
            ulonglong2 h2 = *(const ulonglong2*)&hr2[k];
            ulonglong2 h3 = *(const ulonglong2*)&hr3[k];
            ulonglong2 w0 = *(const ulonglong2*)&wg0[k];
            ulonglong2 w1 = *(const ulonglong2*)&wg1[k];
            ulonglong2 w2 = *(const ulonglong2*)&wg2[k];
            ulonglong2 w3 = *(const ulonglong2*)&wg3[k];
            A00 = ffma2(h0.x, w0.x, A00); A00 = ffma2(h0.y, w0.y, A00);
            A01 = ffma2(h1.x, w0.x, A01); A01 = ffma2(h1.y, w0.y, A01);
            A02 = ffma2(h2.x, w0.x, A02); A02 = ffma2(h2.y, w0.y, A02);
            A03 = ffma2(h3.x, w0.x, A03); A03 = ffma2(h3.y, w0.y, A03);
            A10 = ffma2(h0.x, w1.x, A10); A10 = ffma2(h0.y, w1.y, A10);
            A11 = ffma2(h1.x, w1.x, A11); A11 = ffma2(h1.y, w1.y, A11);
            A12 = ffma2(h2.x, w1.x, A12); A12 = ffma2(h2.y, w1.y, A12);
            A13 = ffma2(h3.x, w1.x, A13); A13 = ffma2(h3.y, w1.y, A13);
            A20 = ffma2(h0.x, w2.x, A20); A20 = ffma2(h0.y, w2.y, A20);
            A21 = ffma2(h1.x, w2.x, A21); A21 = ffma2(h1.y, w2.y, A21);
            A22 = ffma2(h2.x, w2.x, A22); A22 = ffma2(h2.y, w2.y, A22);
            A23 = ffma2(h3.x, w2.x, A23); A23 = ffma2(h3.y, w2.y, A23);
            A30 = ffma2(h0.x, w3.x, A30); A30 = ffma2(h0.y, w3.y, A30);
            A31 = ffma2(h1.x, w3.x, A31); A31 = ffma2(h1.y, w3.y, A31);
            A32 = ffma2(h2.x, w3.x, A32); A32 = ffma2(h2.y, w3.y, A32);
            A33 = ffma2(h3.x, w3.x, A33); A33 = ffma2(h3.y, w3.y, A33);
        }
        float v00,v01,v02,v03, v10,v11,v12,v13, v20,v21,v22,v23, v30,v31,v32,v33;
        { float2 u;
          u = unpk(A00); v00 = u.x + u.y;  u = unpk(A01); v01 = u.x + u.y;
          u = unpk(A02); v02 = u.x + u.y;  u = unpk(A03); v03 = u.x + u.y;
          u = unpk(A10); v10 = u.x + u.y;  u = unpk(A11); v11 = u.x + u.y;
          u = unpk(A12); v12 = u.x + u.y;  u = unpk(A13); v13 = u.x + u.y;
          u = unpk(A20); v20 = u.x + u.y;  u = unpk(A21); v21 = u.x + u.y;
          u = unpk(A22); v22 = u.x + u.y;  u = unpk(A23); v23 = u.x + u.y;
          u = unpk(A30); v30 = u.x + u.y;  u = unpk(A31); v31 = u.x + u.y;
          u = unpk(A32); v32 = u.x + u.y;  u = unpk(A33); v33 = u.x + u.y; }
        // allreduce over the 8 ksl lanes (offsets 1,2,4)
        #pragma unroll
        for (int off = 1; off <= 4; off <<= 1) {
            v00 += __shfl_xor_sync(0xffffffffu, v00, off);
            v01 += __shfl_xor_sync(0xffffffffu, v01, off);
            v02 += __shfl_xor_sync(0xffffffffu, v02, off);
            v03 += __shfl_xor_sync(0xffffffffu, v03, off);
            v10 += __shfl_xor_sync(0xffffffffu, v10, off);
            v11 += __shfl_xor_sync(0xffffffffu, v11, off);
            v12 += __shfl_xor_sync(0xffffffffu, v12, off);
            v13 += __shfl_xor_sync(0xffffffffu, v13, off);
            v20 += __shfl_xor_sync(0xffffffffu, v20, off);
            v21 += __shfl_xor_sync(0xffffffffu, v21, off);
            v22 += __shfl_xor_sync(0xffffffffu, v22, off);
            v23 += __shfl_xor_sync(0xffffffffu, v23, off);
            v30 += __shfl_xor_sync(0xffffffffu, v30, off);
            v31 += __shfl_xor_sync(0xffffffffu, v31, off);
            v32 += __shfl_xor_sync(0xffffffffu, v32, off);
            v33 += __shfl_xor_sync(0xffffffffu, v33, off);
        }

        // prefetch next step's xp (independent of the grid barrier)
        float nx0=0.f, nx1=0.f, nx2=0.f, nx3=0.f;
        if (s + 1 < Tv && act) {
            int tn = dir ? (Tv-2 - s) : (s + 1);
            const float* p = xp + xbase + (size_t)tn*2048;
            nx0 = p[0]; nx1 = p[512]; nx2 = p[1024]; nx3 = p[1536];
        }

        if (act) {
            float gi = SEL4(v00, v01, v02, v03, isel) + xq0;
            float gf = SEL4(v10, v11, v12, v13, isel) + xq1;
            float gg = SEL4(v20, v21, v22, v23, isel) + xq2;
            float go = SEL4(v30, v31, v32, v33, isel) + xq3;
            float iv = fast_sig(gi);
            float fv = fast_sig(gf);
            float gv = fast_tanh(gg);
            float ov = fast_sig(go);
            c = fv * c + iv * gv;
            hout[hwb + (size_t)t*1024] = ov * fast_tanh(c);
        }
        xq0 = nx0; xq1 = nx1; xq2 = nx2; xq3 = nx3;

        // arrive: CTA barrier orders all STGs, then one release-red on counter
        __syncthreads();
        if (tid == 0) red_release(ctr);
    }
}

// ---------------- LayerNorm + ReLU (warp per row of 512) ----------------
__global__ __launch_bounds__(256) void k_lnrelu(const float* __restrict__ in,
                                                const float* __restrict__ lnw,
                                                const float* __restrict__ lnb,
                                                float* __restrict__ out)
{
    int row  = blockIdx.x * 8 + (threadIdx.x >> 5);
    int lane = threadIdx.x & 31;
    const float* p = in + (size_t)row * 512;
    float4 v[4];
    float s = 0.f, s2 = 0.f;
    #pragma unroll
    for (int i = 0; i < 4; i++) {
        v[i] = *(const float4*)&p[i*128 + lane*4];
        s  += v[i].x + v[i].y + v[i].z + v[i].w;
        s2 += v[i].x*v[i].x + v[i].y*v[i].y + v[i].z*v[i].z + v[i].w*v[i].w;
    }
    #pragma unroll
    for (int o = 16; o; o >>= 1) {
        s  += __shfl_xor_sync(0xffffffffu, s,  o);
        s2 += __shfl_xor_sync(0xffffffffu, s2, o);
    }
    float mu   = s * (1.f/512.f);
    float var  = s2 * (1.f/512.f) - mu*mu;
    float rstd = rsqrtf(var + 1e-5f);
    float* q = out + (size_t)row * 512;
    #pragma unroll
    for (int i = 0; i < 4; i++) {
        int k = i*128 + lane*4;
        float4 wv = *(const float4*)&lnw[k];
        float4 bv = *(const float4*)&lnb[k];
        float4 o4;
        o4.x = fmaxf((v[i].x - mu)*rstd*wv.x + bv.x, 0.f);
        o4.y = fmaxf((v[i].y - mu)*rstd*wv.y + bv.y, 0.f);
        o4.z = fmaxf((v[i].z - mu)*rstd*wv.z + bv.z, 0.f);
        o4.w = fmaxf((v[i].w - mu)*rstd*wv.w + bv.w, 0.f);
        *(float4*)&q[k] = o4;
    }
}

// ---------------- host ----------------
extern "C" void kernel_launch(void* const* d_in, const int* in_sizes, int n_in,
                              void* d_out, int out_size)
{
    const float* x       = (const float*)d_in[0];
    const float* wih_l0f = (const float*)d_in[1];
    const float* whh_l0f = (const float*)d_in[2];
    const float* b_l0f   = (const float*)d_in[3];
    const float* wih_l0b = (const float*)d_in[4];
    const float* whh_l0b = (const float*)d_in[5];
    const float* b_l0b   = (const float*)d_in[6];
    const float* wih_l1f = (const float*)d_in[7];
    const float* whh_l1f = (const float*)d_in[8];
    const float* b_l1f   = (const float*)d_in[9];
    const float* wih_l1b = (const float*)d_in[10];
    const float* whh_l1b = (const float*)d_in[11];
    const float* b_l1b   = (const float*)d_in[12];
    const float* fc_w    = (const float*)d_in[13];
    const float* fc_b    = (const float*)d_in[14];
    const float* ln_w    = (const float*)d_in[15];
    const float* ln_b    = (const float*)d_in[16];
    float* out = (float*)d_out;

    void *p_xt, *p_xpf, *p_xpb, *p_h0, *p_h1, *p_fc, *p_cA, *p_cB;
    cudaGetSymbolAddress(&p_xt,  g_xt);
    cudaGetSymbolAddress(&p_xpf, g_xpf);
    cudaGetSymbolAddress(&p_xpb, g_xpb);
    cudaGetSymbolAddress(&p_h0,  g_h0);
    cudaGetSymbolAddress(&p_h1,  g_h1);
    cudaGetSymbolAddress(&p_fc,  g_fc);
    cudaGetSymbolAddress(&p_cA,  g_ctrA);
    cudaGetSymbolAddress(&p_cB,  g_ctrB);

    const size_t LSTM_SMEM = (32*544 + 16*544) * sizeof(float); // 104448 B
    cudaFuncSetAttribute(k_lstm, cudaFuncAttributeMaxDynamicSharedMemorySize, (int)LSTM_SMEM);

    // 1: transpose input (+ reset both layers' barrier counters)
    k_transpose<<<dim3(19, 16, 16), dim3(32, 8)>>>(x);

    // 2: layer 0 fwd projection (full)
    k_gemm<<<dim3(16, 75), 256>>>((const float*)p_xt, wih_l0f, b_l0f, (float*)p_xpf, 512, 2048);
    // 3,4: layer 0 bwd projection split in two N-halves (launch #4 = profiled GEMM)
    k_gemm<<<dim3(8, 75), 256>>>((const float*)p_xt, wih_l0b, b_l0b, (float*)p_xpb, 512, 2048);
    k_gemm<<<dim3(8, 75), 256>>>((const float*)p_xt, wih_l0b + (size_t)1024*512,
                                 b_l0b + 1024, (float*)p_xpb + 1024, 512, 2048);
    // 5: layer 0 recurrence
    k_lstm<<<128, 256, LSTM_SMEM>>>((const float*)p_xpf, (const float*)p_xpb,
                                    whh_l0f, whh_l0b, (float*)p_h0, (unsigned*)p_cA);
    // 6,7: layer 1 input projections (K = 1024)
    k_gemm<<<dim3(16, 75), 256>>>((const float*)p_h0, wih_l1f, b_l1f, (float*)p_xpf, 1024, 2048);
    k_gemm<<<dim3(16, 75), 256>>>((const float*)p_h0, wih_l1b, b_l1b, (float*)p_xpb, 1024, 2048);
    // 8: layer 1 recurrence
    k_lstm<<<128, 256, LSTM_SMEM>>>((const float*)p_xpf, (const float*)p_xpb,
                                    whh_l1f, whh_l1b, (float*)p_h1, (unsigned*)p_cB);
    // 9,10: fc + layernorm + relu
    k_gemm<<<dim3(4, 75), 256>>>((const float*)p_h1, fc_w, fc_b, (float*)p_fc, 1024, 512);
    k_lnrelu<<<1200, 256>>>((const float*)p_fc, ln_w, ln_b, out);
}

// round 8
// speedup vs baseline: 2.7498x; 1.0067x over previous
#include <cuda_runtime.h>
#include <math.h>

#define Bv 16
#define Tv 600
#define Hv 512
#define Mv (Bv*Tv)          // 9600 rows
#define G4 (4*Hv)           // 2048 gate rows
#define RS 576              // LSTM smem row stride: 16 k-slices x 36 floats

// ---------------- scratch (device globals; no allocation) ----------------
__device__ float g_xt [Mv*Hv];        // x transposed [B*T, 512]
__device__ float g_xpf[Mv*G4];        // input-proj fwd  [B*T, 2048]
__device__ float g_xpb[Mv*G4];        // input-proj bwd
__device__ float g_h0 [Mv*2*Hv];      // layer0 output concat [B*T, 1024]
__device__ float g_h1 [Mv*2*Hv];      // layer1 output concat
__device__ float g_fc [Mv*Hv];        // fc output pre-LN
__device__ unsigned g_ctrA[64];       // layer0 step counters
__device__ unsigned g_ctrB[64];       // layer1 step counters

// ---------------- helpers ----------------
__device__ __forceinline__ unsigned long long ffma2(unsigned long long a,
                                                    unsigned long long b,
                                                    unsigned long long c)
{
    unsigned long long d;
    asm("fma.rn.f32x2 %0, %1, %2, %3;" : "=l"(d) : "l"(a), "l"(b), "l"(c));
    return d;
}
__device__ __forceinline__ float2 unpk(unsigned long long v)
{
    float2 r;
    asm("mov.b64 {%0, %1}, %2;" : "=f"(r.x), "=f"(r.y) : "l"(v));
    return r;
}
__device__ __forceinline__ unsigned ld_acq(const unsigned* p)
{
    unsigned v;
    asm volatile("ld.acquire.gpu.global.u32 %0, [%1];" : "=r"(v) : "l"(p));
    return v;
}
__device__ __forceinline__ void red_release(unsigned* p)
{
    asm volatile("red.release.gpu.global.add.u32 [%0], 1;" :: "l"(p) : "memory");
}
__device__ __forceinline__ float fast_sig(float x)
{
    return __fdividef(1.f, 1.f + __expf(-x));
}
__device__ __forceinline__ float fast_tanh(float x)
{
    return 1.f - 2.f * __fdividef(1.f, __expf(2.f * x) + 1.f);
}
// 8-way register select by 3 predicate bits (compiles to SELs)
#define SEL8(vv, c0, c1, c2, out) do {                    \
    float _x0 = (c0) ? (vv)[1] : (vv)[0];                 \
    float _x1 = (c0) ? (vv)[3] : (vv)[2];                 \
    float _x2 = (c0) ? (vv)[5] : (vv)[4];                 \
    float _x3 = (c0) ? (vv)[7] : (vv)[6];                 \
    float _y0 = (c1) ? _x1 : _x0;                         \
    float _y1 = (c1) ? _x3 : _x2;                         \
    (out) = (c2) ? _y1 : _y0;                             \
} while (0)

// ---------------- transpose x[B,H,T] -> g_xt + counter reset ----------------
__global__ void k_transpose(const float* __restrict__ x)
{
    if (blockIdx.x == 0 && blockIdx.y == 0 && blockIdx.z == 0) {
        int id = threadIdx.y * 32 + threadIdx.x;
        if (id < 64)       g_ctrA[id] = 0u;
        else if (id < 128) g_ctrB[id - 64] = 0u;
    }
    __shared__ float tile[32][33];
    int bb = blockIdx.z;
    int t0 = blockIdx.x * 32, h0 = blockIdx.y * 32;
    int tx = threadIdx.x, ty = threadIdx.y;
    #pragma unroll
    for (int i = 0; i < 4; i++) {
        int hh = h0 + ty + i*8;
        int tt = t0 + tx;
        if (tt < Tv) tile[ty + i*8][tx] = x[(bb*Hv + hh)*Tv + tt];
    }
    __syncthreads();
    #pragma unroll
    for (int i = 0; i < 4; i++) {
        int tt = t0 + ty + i*8;
        int hh = h0 + tx;
        if (tt < Tv) g_xt[(bb*Tv + tt)*Hv + hh] = tile[tx][ty + i*8];
    }
}

// ---------------- persistent GEMM: C[M,N] = A @ W^T + bias ----------------
// BM=128, BN=128, BK=16, 256 threads, 8x8/thread (two 4x4 quads). Grid = 296
// CTAs loop over tiles; optional second (W,bias,C) set for merged launches.
__global__ __launch_bounds__(256, 2) void k_gemm(const float* __restrict__ A,
                                                 int K, int N,
                                                 const float* __restrict__ W1,
                                                 const float* __restrict__ b1,
                                                 float* __restrict__ C1, int nt1,
                                                 const float* __restrict__ W2,
                                                 const float* __restrict__ b2,
                                                 float* __restrict__ C2, int ntot)
{
    __shared__ __align__(16) float As[16][132];
    __shared__ __align__(16) float Ws[16][132];
    const int tid = threadIdx.x;
    const int tx = tid & 15;
    const int ty = tid >> 4;

    for (int t = blockIdx.x; t < ntot; t += gridDim.x) {
        const float* W; const float* bias; float* C; int tt;
        if (t < nt1) { W = W1; bias = b1; C = C1; tt = t; }
        else         { W = W2; bias = b2; C = C2; tt = t - nt1; }
        const int m0 = (tt % 75) * 128;
        const int n0 = (tt / 75) * 128;

        float acc[8][8] = {};
        for (int kb = 0; kb < K; kb += 16) {
            #pragma unroll
            for (int i = 0; i < 2; i++) {
                int s = tid + i*256;
                int r = s >> 2, k4 = (s & 3) * 4;
                float4 v = *(const float4*)&A[(size_t)(m0 + r)*K + kb + k4];
                As[k4+0][r] = v.x; As[k4+1][r] = v.y;
                As[k4+2][r] = v.z; As[k4+3][r] = v.w;
                float4 u = *(const float4*)&W[(size_t)(n0 + r)*K + kb + k4];
                Ws[k4+0][r] = u.x; Ws[k4+1][r] = u.y;
                Ws[k4+2][r] = u.z; Ws[k4+3][r] = u.w;
            }
            __syncthreads();
            #pragma unroll
            for (int k = 0; k < 16; k++) {
                float4 a0 = *(const float4*)&As[k][ty*4];
                float4 a1 = *(const float4*)&As[k][64 + ty*4];
                float4 w0 = *(const float4*)&Ws[k][tx*4];
                float4 w1 = *(const float4*)&Ws[k][64 + tx*4];
                float am[8] = {a0.x,a0.y,a0.z,a0.w,a1.x,a1.y,a1.z,a1.w};
                float wn[8] = {w0.x,w0.y,w0.z,w0.w,w1.x,w1.y,w1.z,w1.w};
                #pragma unroll
                for (int mi = 0; mi < 8; mi++) {
                    #pragma unroll
                    for (int ni = 0; ni < 8; ni++)
                        acc[mi][ni] = fmaf(am[mi], wn[ni], acc[mi][ni]);
                }
            }
            __syncthreads();
        }
        float4 bv0 = *(const float4*)&bias[n0 + tx*4];
        float4 bv1 = *(const float4*)&bias[n0 + 64 + tx*4];
        #pragma unroll
        for (int mi = 0; mi < 8; mi++) {
            int row = m0 + ((mi < 4) ? (ty*4 + mi) : (64 + ty*4 + mi - 4));
            float4 o0, o1;
            o0.x = acc[mi][0] + bv0.x; o0.y = acc[mi][1] + bv0.y;
            o0.z = acc[mi][2] + bv0.z; o0.w = acc[mi][3] + bv0.w;
            o1.x = acc[mi][4] + bv1.x; o1.y = acc[mi][5] + bv1.y;
            o1.z = acc[mi][6] + bv1.z; o1.w = acc[mi][7] + bv1.w;
            *(float4*)&C[(size_t)row*N + n0 + tx*4]      = o0;
            *(float4*)&C[(size_t)row*N + n0 + 64 + tx*4] = o1;
        }
    }
}

// ---------------- persistent bidirectional LSTM layer ----------------
// 128 blocks: [0,64) fwd, [64,128) bwd. Block owns 8 hidden units; warp wi =
// unit. lane = bq*16 + ksl: thread computes 4 gates x 8 batches (bq*8..+7)
// over k-slice [ksl*32, ksl*32+32). k-slices padded to 36 floats (9 quads,
// gcd(9,8)=1 -> conflict-free). 4-round shfl_xor allreduce over 16 ksl lanes;
// lanes with (lane&8)==0 do the cell update (batch = bq*8 + (lane&7)).
__global__ __launch_bounds__(256, 1) void k_lstm(const float* __restrict__ xpf,
                                                 const float* __restrict__ xpb,
                                                 const float* __restrict__ whhf,
                                                 const float* __restrict__ whhb,
                                                 float* __restrict__ hout,
                                                 unsigned* __restrict__ ctrbase)
{
    extern __shared__ float sm[];
    float* w_s = sm;                  // [32][RS]
    float* h_s = w_s + 32*RS;         // [16][RS]

    const int tid   = threadIdx.x;
    const int bid   = blockIdx.x;
    const int dir   = bid >> 6;
    const int u0    = (bid & 63) * 8;
    const float* xp  = dir ? xpb  : xpf;
    const float* whh = dir ? whhb : whhf;
    unsigned* ctr = ctrbase + dir * 32;

    // stage w_hh slice: 32 rows x 512 (row lr: gate=lr>>3, j=lr&7)
    for (int idx = tid; idx < 32*128; idx += 256) {
        int lr = idx >> 7, k = (idx & 127) * 4;
        int gr = (lr >> 3) * 512 + u0 + (lr & 7);
        float4 v = *(const float4*)&whh[(size_t)gr * 512 + k];
        *(float4*)&w_s[lr*RS + (k >> 5)*36 + (k & 31)] = v;
    }

    const int lane = tid & 31;
    const int wi   = tid >> 5;        // unit j = wi
    const int ksl  = lane & 15;       // k-slice (32 wide)
    const int bq   = lane >> 4;       // batch octet
    const int kof  = ksl * 36;
    const float* wg0 = w_s + (0*8 + wi)*RS + kof;
    const float* wg1 = w_s + (1*8 + wi)*RS + kof;
    const float* wg2 = w_s + (2*8 + wi)*RS + kof;
    const float* wg3 = w_s + (3*8 + wi)*RS + kof;
    const float* hb  = h_s + bq*8*RS + kof;

    // activation lanes: (lane & 8) == 0; batch = bq*8 + (lane&7)
    const bool act = (lane & 8) == 0;
    const int  bsel = lane & 7;
    const bool c0 = (bsel & 1), c1 = (bsel & 2), c2 = (bsel & 4);
    const int  bmy = bq*8 + bsel;
    const size_t xbase = (size_t)bmy*Tv*2048 + u0 + wi;            // + t*2048 + g*512
    const size_t hwb   = (size_t)bmy*Tv*1024 + dir*512 + u0 + wi;  // + t*1024

    float c = 0.f;
    float xq0=0.f, xq1=0.f, xq2=0.f, xq3=0.f;
    {
        int t0i = dir ? (Tv-1) : 0;
        if (act) {
            const float* p = xp + xbase + (size_t)t0i*2048;
            xq0 = p[0]; xq1 = p[512]; xq2 = p[1024]; xq3 = p[1536];
        }
    }

    for (int s = 0; s < Tv; s++) {
        int t = dir ? (Tv-1 - s) : s;
        if (s > 0) {
            if (tid == 0) {
                unsigned target = 64u * (unsigned)s;
                while ((int)(ld_acq(ctr) - target) < 0) { }
            }
            __syncthreads();
            int tp = dir ? t + 1 : t - 1;
            for (int idx = tid; idx < 2048; idx += 256) {
                int bb = idx >> 7, k = (idx & 127) * 4;
                *(float4*)&h_s[bb*RS + (k >> 5)*36 + (k & 31)] =
                    *(const float4*)&hout[(size_t)(bb*Tv + tp)*1024 + dir*512 + k];
            }
        } else {
            for (int idx = tid; idx < 16*RS; idx += 256) h_s[idx] = 0.f;
        }
        __syncthreads();

        // 4 gates x 8 batches over this thread's 32-k slice (packed f32x2)
        unsigned long long A[4][8];
        #pragma unroll
        for (int g = 0; g < 4; g++)
            #pragma unroll
            for (int b = 0; b < 8; b++) A[g][b] = 0ull;

        #pragma unroll 2
        for (int k = 0; k < 32; k += 4) {
            ulonglong2 w0 = *(const ulonglong2*)&wg0[k];
            ulonglong2 w1 = *(const ulonglong2*)&wg1[k];
            ulonglong2 w2 = *(const ulonglong2*)&wg2[k];
            ulonglong2 w3 = *(const ulonglong2*)&wg3[k];
            #pragma unroll
            for (int b = 0; b < 8; b++) {
                ulonglong2 hv = *(const ulonglong2*)&hb[b*RS + k];
                A[0][b] = ffma2(hv.x, w0.x, A[0][b]); A[0][b] = ffma2(hv.y, w0.y, A[0][b]);
                A[1][b] = ffma2(hv.x, w1.x, A[1][b]); A[1][b] = ffma2(hv.y, w1.y, A[1][b]);
                A[2][b] = ffma2(hv.x, w2.x, A[2][b]); A[2][b] = ffma2(hv.y, w2.y, A[2][b]);
                A[3][b] = ffma2(hv.x, w3.x, A[3][b]); A[3][b] = ffma2(hv.y, w3.y, A[3][b]);
            }
        }
        float v[4][8];
        #pragma unroll
        for (int g = 0; g < 4; g++)
            #pragma unroll
            for (int b = 0; b < 8; b++) {
                float2 u = unpk(A[g][b]);
                v[g][b] = u.x + u.y;
            }
        // allreduce over the 16 ksl lanes (offsets 1,2,4,8)
        #pragma unroll
        for (int off = 1; off <= 8; off <<= 1)
            #pragma unroll
            for (int g = 0; g < 4; g++)
                #pragma unroll
                for (int b = 0; b < 8; b++)
                    v[g][b] += __shfl_xor_sync(0xffffffffu, v[g][b], off);

        // prefetch next step's xp (independent of the grid barrier)
        float nx0=0.f, nx1=0.f, nx2=0.f, nx3=0.f;
        if (s + 1 < Tv && act) {
            int tn = dir ? (Tv-2 - s) : (s + 1);
            const float* p = xp + xbase + (size_t)tn*2048;
            nx0 = p[0]; nx1 = p[512]; nx2 = p[1024]; nx3 = p[1536];
        }

        if (act) {
            float gi, gf, gg, go;
            SEL8(v[0], c0, c1, c2, gi);
            SEL8(v[1], c0, c1, c2, gf);
            SEL8(v[2], c0, c1, c2, gg);
            SEL8(v[3], c0, c1, c2, go);
            gi += xq0; gf += xq1; gg += xq2; go += xq3;
            float iv = fast_sig(gi);
            float fv = fast_sig(gf);
            float gv = fast_tanh(gg);
            float ov = fast_sig(go);
            c = fv * c + iv * gv;
            hout[hwb + (size_t)t*1024] = ov * fast_tanh(c);
        }
        xq0 = nx0; xq1 = nx1; xq2 = nx2; xq3 = nx3;

        // arrive: CTA barrier orders all STGs, then one release-red on counter
        __syncthreads();
        if (tid == 0) red_release(ctr);
    }
}

// ---------------- LayerNorm + ReLU (warp per row of 512) ----------------
__global__ __launch_bounds__(256) void k_lnrelu(const float* __restrict__ in,
                                                const float* __restrict__ lnw,
                                                const float* __restrict__ lnb,
                                                float* __restrict__ out)
{
    int row  = blockIdx.x * 8 + (threadIdx.x >> 5);
    int lane = threadIdx.x & 31;
    const float* p = in + (size_t)row * 512;
    float4 v[4];
    float s = 0.f, s2 = 0.f;
    #pragma unroll
    for (int i = 0; i < 4; i++) {
        v[i] = *(const float4*)&p[i*128 + lane*4];
        s  += v[i].x + v[i].y + v[i].z + v[i].w;
        s2 += v[i].x*v[i].x + v[i].y*v[i].y + v[i].z*v[i].z + v[i].w*v[i].w;
    }
    #pragma unroll
    for (int o = 16; o; o >>= 1) {
        s  += __shfl_xor_sync(0xffffffffu, s,  o);
        s2 += __shfl_xor_sync(0xffffffffu, s2, o);
    }
    float mu   = s * (1.f/512.f);
    float var  = s2 * (1.f/512.f) - mu*mu;
    float rstd = rsqrtf(var + 1e-5f);
    float* q = out + (size_t)row * 512;
    #pragma unroll
    for (int i = 0; i < 4; i++) {
        int k = i*128 + lane*4;
        float4 wv = *(const float4*)&lnw[k];
        float4 bv = *(const float4*)&lnb[k];
        float4 o4;
        o4.x = fmaxf((v[i].x - mu)*rstd*wv.x + bv.x, 0.f);
        o4.y = fmaxf((v[i].y - mu)*rstd*wv.y + bv.y, 0.f);
        o4.z = fmaxf((v[i].z - mu)*rstd*wv.z + bv.z, 0.f);
        o4.w = fmaxf((v[i].w - mu)*rstd*wv.w + bv.w, 0.f);
        *(float4*)&q[k] = o4;
    }
}

// ---------------- host ----------------
extern "C" void kernel_launch(void* const* d_in, const int* in_sizes, int n_in,
                              void* d_out, int out_size)
{
    const float* x       = (const float*)d_in[0];
    const float* wih_l0f = (const float*)d_in[1];
    const float* whh_l0f = (const float*)d_in[2];
    const float* b_l0f   = (const float*)d_in[3];
    const float* wih_l0b = (const float*)d_in[4];
    const float* whh_l0b = (const float*)d_in[5];
    const float* b_l0b   = (const float*)d_in[6];
    const float* wih_l1f = (const float*)d_in[7];
    const float* whh_l1f = (const float*)d_in[8];
    const float* b_l1f   = (const float*)d_in[9];
    const float* wih_l1b = (const float*)d_in[10];
    const float* whh_l1b = (const float*)d_in[11];
    const float* b_l1b   = (const float*)d_in[12];
    const float* fc_w    = (const float*)d_in[13];
    const float* fc_b    = (const float*)d_in[14];
    const float* ln_w    = (const float*)d_in[15];
    const float* ln_b    = (const float*)d_in[16];
    float* out = (float*)d_out;

    void *p_xt, *p_xpf, *p_xpb, *p_h0, *p_h1, *p_fc, *p_cA, *p_cB;
    cudaGetSymbolAddress(&p_xt,  g_xt);
    cudaGetSymbolAddress(&p_xpf, g_xpf);
    cudaGetSymbolAddress(&p_xpb, g_xpb);
    cudaGetSymbolAddress(&p_h0,  g_h0);
    cudaGetSymbolAddress(&p_h1,  g_h1);
    cudaGetSymbolAddress(&p_fc,  g_fc);
    cudaGetSymbolAddress(&p_cA,  g_ctrA);
    cudaGetSymbolAddress(&p_cB,  g_ctrB);

    const size_t LSTM_SMEM = (32*RS + 16*RS) * sizeof(float); // 110592 B
    cudaFuncSetAttribute(k_lstm, cudaFuncAttributeMaxDynamicSharedMemorySize, (int)LSTM_SMEM);

    const int PGRID = 296;   // 2 CTAs/SM persistent GEMM grid

    // 1: transpose input (+ reset both layers' barrier counters)
    k_transpose<<<dim3(19, 16, 16), dim3(32, 8)>>>(x);

    // 2: layer 0 projections, fwd+bwd merged (1200+1200 tiles, K=512)
    k_gemm<<<PGRID, 256>>>((const float*)p_xt, 512, 2048,
                           wih_l0f, b_l0f, (float*)p_xpf, 1200,
                           wih_l0b, b_l0b, (float*)p_xpb, 2400);
    // 3: layer 0 recurrence
    k_lstm<<<128, 256, LSTM_SMEM>>>((const float*)p_xpf, (const float*)p_xpb,
                                    whh_l0f, whh_l0b, (float*)p_h0, (unsigned*)p_cA);
    // 4: layer 1 projections, fwd+bwd merged (K=1024)
    k_gemm<<<PGRID, 256>>>((const float*)p_h0, 1024, 2048,
                           wih_l1f, b_l1f, (float*)p_xpf, 1200,
                           wih_l1b, b_l1b, (float*)p_xpb, 2400);
    // 5: layer 1 recurrence
    k_lstm<<<128, 256, LSTM_SMEM>>>((const float*)p_xpf, (const float*)p_xpb,
                                    whh_l1f, whh_l1b, (float*)p_h1, (unsigned*)p_cB);
    // 6: fc (300 tiles, K=1024, N=512)
    k_gemm<<<PGRID, 256>>>((const float*)p_h1, 1024, 512,
                           fc_w, fc_b, (float*)p_fc, 300,
                           fc_w, fc_b, (float*)p_fc, 300);
    // 7: layernorm + relu
    k_lnrelu<<<1200, 256>>>((const float*)p_fc, ln_w, ln_b, out);
}